// round 3
// baseline (speedup 1.0000x reference)
#include <cuda_runtime.h>
#include <cuda_bf16.h>
#include <math.h>

// ---------------- problem constants ----------------
#define NN   4096
#define HID  256
#define NH   4
#define DD   64
#define DEG  32
#define EE   (NN * DEG)

// ---------------- scratch (device globals; no allocation) ----------------
__device__ float g_q [NN * HID];
__device__ float g_k [NN * HID];
__device__ float g_v [NN * HID];
__device__ float g_ao[NN * HID];     // attention output (pre-Wo)
__device__ float g_ot[NN * HID];     // Wo output
__device__ float g_x1[NN * HID];     // after first LN
__device__ float g_h1[NN * 4 * HID]; // FFN hidden
__device__ float g_f2[NN * HID];     // FFN output

// ---------------- SGEMM: C[M,N] = A[M,K] @ B[K,N] + bias, optional ReLU ----
// BM=64, BN=64, BK=16, 256 threads, 4x4 microtile per thread.
template <bool RELU>
__global__ __launch_bounds__(256)
void sgemm_kernel(const float* __restrict__ A, const float* __restrict__ B,
                  const float* __restrict__ bias, float* __restrict__ C,
                  int M, int K, int Nd)
{
    __shared__ float As[16][64];
    __shared__ float Bs[16][64];

    const int tid = threadIdx.x;
    const int bm  = blockIdx.y * 64;
    const int bn  = blockIdx.x * 64;

    const int tx = tid & 15;   // 0..15 -> 4 cols each
    const int ty = tid >> 4;   // 0..15 -> 4 rows each

    // load mapping
    const int aRow = tid >> 2;        // 0..63
    const int aCol = (tid & 3) * 4;   // 0,4,8,12
    const int bRow = tid >> 4;        // 0..15
    const int bCol = (tid & 15) * 4;  // 0..60

    const float* aPtr = A + (size_t)(bm + aRow) * K + aCol;
    const float* bPtr = B + (size_t)bRow * Nd + bn + bCol;
    const size_t bStep = (size_t)16 * Nd;

    float acc[4][4];
#pragma unroll
    for (int i = 0; i < 4; i++)
#pragma unroll
        for (int j = 0; j < 4; j++) acc[i][j] = 0.f;

    for (int k0 = 0; k0 < K; k0 += 16) {
        float4 av = *(const float4*)(aPtr + k0);
        As[aCol + 0][aRow] = av.x;
        As[aCol + 1][aRow] = av.y;
        As[aCol + 2][aRow] = av.z;
        As[aCol + 3][aRow] = av.w;
        float4 bv = *(const float4*)bPtr;
        bPtr += bStep;
        *(float4*)(&Bs[bRow][bCol]) = bv;
        __syncthreads();

#pragma unroll
        for (int kk = 0; kk < 16; kk++) {
            float a[4], b[4];
#pragma unroll
            for (int i = 0; i < 4; i++) a[i] = As[kk][ty * 4 + i];
#pragma unroll
            for (int j = 0; j < 4; j++) b[j] = Bs[kk][tx * 4 + j];
#pragma unroll
            for (int i = 0; i < 4; i++)
#pragma unroll
                for (int j = 0; j < 4; j++) acc[i][j] = fmaf(a[i], b[j], acc[i][j]);
        }
        __syncthreads();
    }

    // epilogue
    const int colBase = bn + tx * 4;
    float4 bb = *(const float4*)(bias + colBase);
#pragma unroll
    for (int i = 0; i < 4; i++) {
        const int row = bm + ty * 4 + i;
        float4 cv;
        cv.x = acc[i][0] + bb.x;
        cv.y = acc[i][1] + bb.y;
        cv.z = acc[i][2] + bb.z;
        cv.w = acc[i][3] + bb.w;
        if (RELU) {
            cv.x = fmaxf(cv.x, 0.f); cv.y = fmaxf(cv.y, 0.f);
            cv.z = fmaxf(cv.z, 0.f); cv.w = fmaxf(cv.w, 0.f);
        }
        *(float4*)(C + (size_t)row * Nd + colBase) = cv;
    }
}

// ---------------- attention: one block per node, one warp per head --------
// Edges for node n are exactly [n*32, n*32+32) (src = repeat(arange(N), 32)).
// Lane j owns edge j: computes its logit (q.k/8 + edge_bias), warp softmax,
// then the weighted sum over v is done cooperatively (coalesced v reads).
__global__ __launch_bounds__(128)
void attn_kernel(const float* __restrict__ q, const float* __restrict__ k,
                 const float* __restrict__ v, const void* __restrict__ ei,
                 const float* __restrict__ edge_attr,
                 const float* __restrict__ We, const float* __restrict__ be,
                 float* __restrict__ out)
{
    const int node = blockIdx.x;
    const int h    = threadIdx.y;   // 0..3
    const int lane = threadIdx.x;   // 0..31

    __shared__ float sq[NH][DD];

    // detect int64 vs int32 edge_index layout:
    // int64: int32-view element (2E-1) is the high word of src[E-1]=4095 -> 0.
    // int32: that element is dst[E-1]=31 -> nonzero.
    const int probe = ((const int*)ei)[2 * EE - 1];
    const bool is64 = (probe == 0);

    const int e = node * DEG + lane;
    int dst;
    if (is64) dst = (int)((const long long*)ei)[EE + e];
    else      dst = ((const int*)ei)[EE + e];

    // edge bias for my edge
    float eb = be[h];
    const float* ea = edge_attr + (size_t)e * 16;
#pragma unroll
    for (int c = 0; c < 16; c++) eb = fmaf(ea[c], We[c * NH + h], eb);

    // stage q head-slice into shared (warp-local use only)
    {
        float2 qf = *(const float2*)(q + (size_t)node * HID + h * DD + lane * 2);
        sq[h][lane * 2]     = qf.x;
        sq[h][lane * 2 + 1] = qf.y;
    }
    __syncwarp();

    // per-lane dot product with its own dst row
    const float* krow = k + (size_t)dst * HID + h * DD;
    float dotv = 0.f;
#pragma unroll
    for (int d0 = 0; d0 < DD; d0 += 4) {
        float4 kf = *(const float4*)(krow + d0);
        dotv = fmaf(sq[h][d0],     kf.x, dotv);
        dotv = fmaf(sq[h][d0 + 1], kf.y, dotv);
        dotv = fmaf(sq[h][d0 + 2], kf.z, dotv);
        dotv = fmaf(sq[h][d0 + 3], kf.w, dotv);
    }
    float logit = dotv * 0.125f + eb;   // 1/sqrt(64)

    // warp softmax over the 32 edges
    float m = logit;
#pragma unroll
    for (int o = 16; o; o >>= 1) m = fmaxf(m, __shfl_xor_sync(0xffffffffu, m, o));
    float p = __expf(logit - m);
    float s = p;
#pragma unroll
    for (int o = 16; o; o >>= 1) s += __shfl_xor_sync(0xffffffffu, s, o);
    const float prob = p / s;

    // weighted sum of v (coalesced: each lane owns 2 consecutive d-elements)
    float accx = 0.f, accy = 0.f;
#pragma unroll 8
    for (int j = 0; j < DEG; j++) {
        const int   dj = __shfl_sync(0xffffffffu, dst,  j);
        const float pj = __shfl_sync(0xffffffffu, prob, j);
        float2 vf = *(const float2*)(v + (size_t)dj * HID + h * DD + lane * 2);
        accx = fmaf(pj, vf.x, accx);
        accy = fmaf(pj, vf.y, accy);
    }
    float2 o2; o2.x = accx; o2.y = accy;
    *(float2*)(out + (size_t)node * HID + h * DD + lane * 2) = o2;
}

// ---------------- residual + LayerNorm: one block (256 thr) per row -------
__global__ __launch_bounds__(256)
void ln_kernel(const float* __restrict__ x, const float* __restrict__ res,
               const float* __restrict__ g, const float* __restrict__ b,
               float* __restrict__ out)
{
    const int row = blockIdx.x;
    const int t   = threadIdx.x;

    const float val = x[(size_t)row * HID + t] + res[(size_t)row * HID + t];

    __shared__ float red[16];   // [0..7] sums, [8..15] sumsq
    float s  = val;
    float q2 = val * val;
#pragma unroll
    for (int o = 16; o; o >>= 1) {
        s  += __shfl_xor_sync(0xffffffffu, s,  o);
        q2 += __shfl_xor_sync(0xffffffffu, q2, o);
    }
    const int w = t >> 5, l = t & 31;
    if (l == 0) { red[w] = s; red[8 + w] = q2; }
    __syncthreads();

    float ts = 0.f, tq = 0.f;
#pragma unroll
    for (int i = 0; i < 8; i++) { ts += red[i]; tq += red[8 + i]; }

    const float mean = ts * (1.f / HID);
    const float var  = tq * (1.f / HID) - mean * mean;
    const float r    = rsqrtf(var + 1e-5f);

    out[(size_t)row * HID + t] = (val - mean) * r * g[t] + b[t];
}

// ---------------- launch ----------------
extern "C" void kernel_launch(void* const* d_in, const int* in_sizes, int n_in,
                              void* d_out, int out_size)
{
    const float* x   = (const float*)d_in[0];
    const void*  ei  = d_in[1];
    const float* ea  = (const float*)d_in[2];
    const float* Wq  = (const float*)d_in[3];
    const float* bq  = (const float*)d_in[4];
    const float* Wk  = (const float*)d_in[5];
    const float* bk  = (const float*)d_in[6];
    const float* Wv  = (const float*)d_in[7];
    const float* bv  = (const float*)d_in[8];
    const float* Wo  = (const float*)d_in[9];
    const float* bo  = (const float*)d_in[10];
    const float* We  = (const float*)d_in[11];
    const float* be  = (const float*)d_in[12];
    const float* g1  = (const float*)d_in[13];
    const float* b1  = (const float*)d_in[14];
    const float* g2  = (const float*)d_in[15];
    const float* b2  = (const float*)d_in[16];
    const float* Wf1 = (const float*)d_in[17];
    const float* bf1 = (const float*)d_in[18];
    const float* Wf2 = (const float*)d_in[19];
    const float* bf2 = (const float*)d_in[20];
    float* out = (float*)d_out;

    float *q, *k, *v, *ao, *ot, *x1, *h1, *f2;
    cudaGetSymbolAddress((void**)&q,  g_q);
    cudaGetSymbolAddress((void**)&k,  g_k);
    cudaGetSymbolAddress((void**)&v,  g_v);
    cudaGetSymbolAddress((void**)&ao, g_ao);
    cudaGetSymbolAddress((void**)&ot, g_ot);
    cudaGetSymbolAddress((void**)&x1, g_x1);
    cudaGetSymbolAddress((void**)&h1, g_h1);
    cudaGetSymbolAddress((void**)&f2, g_f2);

    const dim3 gQKV(HID / 64, NN / 64);          // (4, 64)
    const dim3 gF1 (4 * HID / 64, NN / 64);      // (16, 64)
    const dim3 gF2 (HID / 64, NN / 64);          // (4, 64)

    sgemm_kernel<false><<<gQKV, 256>>>(x, Wq, bq, q, NN, HID, HID);
    sgemm_kernel<false><<<gQKV, 256>>>(x, Wk, bk, k, NN, HID, HID);
    sgemm_kernel<false><<<gQKV, 256>>>(x, Wv, bv, v, NN, HID, HID);

    attn_kernel<<<NN, dim3(32, NH)>>>(q, k, v, ei, ea, We, be, ao);

    sgemm_kernel<false><<<gQKV, 256>>>(ao, Wo, bo, ot, NN, HID, HID);

    ln_kernel<<<NN, HID>>>(x, ot, g1, b1, x1);

    sgemm_kernel<true ><<<gF1, 256>>>(x1, Wf1, bf1, h1, NN, HID, 4 * HID);
    sgemm_kernel<false><<<gF2, 256>>>(h1, Wf2, bf2, f2, NN, 4 * HID, HID);

    ln_kernel<<<NN, HID>>>(x1, f2, g2, b2, out);
}

// round 5
// speedup vs baseline: 1.7497x; 1.7497x over previous
#include <cuda_runtime.h>
#include <cuda_bf16.h>
#include <math.h>
#include <stdint.h>

// ---------------- problem constants ----------------
#define NN   4096
#define HID  256
#define NH   4
#define DD   64
#define DEG  32
#define EE   (NN * DEG)

// ---------------- scratch (device globals; no allocation) ----------------
__device__ float g_q [NN * HID];
__device__ float g_k [NN * HID];
__device__ float g_v [NN * HID];
__device__ float g_ao[NN * HID];     // attention output (pre-Wo)
__device__ float g_ot[NN * HID];     // Wo output
__device__ float g_x1[NN * HID];     // after first LN
__device__ float g_h1[NN * 4 * HID]; // FFN hidden
__device__ float g_f2[NN * HID];     // FFN output

// ---------------- helpers ----------------
__device__ __forceinline__ uint32_t f2tf32(float x) {
    uint32_t r;
    asm("cvt.rna.tf32.f32 %0, %1;" : "=r"(r) : "f"(x));
    return r;
}

#define MMA_TF32(d, a0, a1, a2, a3, b0, b1)                                   \
    asm volatile(                                                             \
        "mma.sync.aligned.m16n8k8.row.col.f32.tf32.tf32.f32 "                 \
        "{%0,%1,%2,%3},{%4,%5,%6,%7},{%8,%9},{%0,%1,%2,%3};"                  \
        : "+f"(d[0]), "+f"(d[1]), "+f"(d[2]), "+f"(d[3])                      \
        : "r"(a0), "r"(a1), "r"(a2), "r"(a3), "r"(b0), "r"(b1))

// ---------------- 3xTF32 tensor-core GEMM ----------------
// C[M,N] = A[M,K] @ B[K,N] + bias (+ReLU). BM=128, BN=64, BK=32.
// 256 threads = 8 warps as 4(M) x 2(N); warp tile 32x32 = 2 Mtiles x 4 Ntiles
// of m16n8k8. 3xTF32: acc += ah*bh + al*bh + ah*bl  (fp32-accurate).
template <bool RELU>
__global__ __launch_bounds__(256)
void gemm_tf32(const float* __restrict__ A, const float* __restrict__ B,
               const float* __restrict__ bias, float* __restrict__ C,
               int M, int K, int Nd)
{
    __shared__ __align__(16) float As[128 * 36];   // pad 36: conflict-free A-frag LDS
    __shared__ __align__(16) float Bs[32 * 72];    // pad 72: conflict-free B-frag LDS

    const int tid   = threadIdx.x;
    const int lane  = tid & 31;
    const int wid   = tid >> 5;
    const int warpM = wid >> 1;      // 0..3  (32 rows each)
    const int warpN = wid & 1;       // 0..1  (32 cols each)
    const int bm    = blockIdx.y * 128;
    const int bn    = blockIdx.x * 64;

    // gmem load mappings
    // A tile: 128x32 = 1024 float4 slots, 4 per thread
    const int aRow[4] = { (tid + 0*256) >> 3, (tid + 1*256) >> 3,
                          (tid + 2*256) >> 3, (tid + 3*256) >> 3 };
    const int aC4 = tid & 7;
    // B tile: 32x64 = 512 float4 slots, 2 per thread
    const int bRow[2] = { (tid + 0*256) >> 4, (tid + 1*256) >> 4 };
    const int bC4 = tid & 15;

    float acc[2][4][4];
#pragma unroll
    for (int i = 0; i < 2; i++)
#pragma unroll
        for (int j = 0; j < 4; j++)
#pragma unroll
            for (int r = 0; r < 4; r++) acc[i][j][r] = 0.f;

    const int T = K >> 5;            // K/32 tiles
    float4 pa[4], pb[2];

    // prefetch tile 0
#pragma unroll
    for (int i = 0; i < 4; i++)
        pa[i] = *(const float4*)(A + (size_t)(bm + aRow[i]) * K + aC4 * 4);
#pragma unroll
    for (int i = 0; i < 2; i++)
        pb[i] = *(const float4*)(B + (size_t)bRow[i] * Nd + bn + bC4 * 4);
#pragma unroll
    for (int i = 0; i < 4; i++)
        *(float4*)&As[aRow[i] * 36 + aC4 * 4] = pa[i];
#pragma unroll
    for (int i = 0; i < 2; i++)
        *(float4*)&Bs[bRow[i] * 72 + bC4 * 4] = pb[i];
    __syncthreads();

    for (int t = 0; t < T; t++) {
        if (t + 1 < T) {
            const int k0 = (t + 1) << 5;
#pragma unroll
            for (int i = 0; i < 4; i++)
                pa[i] = *(const float4*)(A + (size_t)(bm + aRow[i]) * K + k0 + aC4 * 4);
#pragma unroll
            for (int i = 0; i < 2; i++)
                pb[i] = *(const float4*)(B + (size_t)(k0 + bRow[i]) * Nd + bn + bC4 * 4);
        }

#pragma unroll
        for (int ks = 0; ks < 4; ks++) {
            // A fragments: rows warpM*32 + im*16 + {l/4, l/4+8}, cols ks*8 + {l%4, l%4+4}
            uint32_t ah[2][4], al[2][4];
#pragma unroll
            for (int im = 0; im < 2; im++) {
                const int r0 = warpM * 32 + im * 16 + (lane >> 2);
                const int c0 = ks * 8 + (lane & 3);
                float a0 = As[(r0    ) * 36 + c0    ];
                float a1 = As[(r0 + 8) * 36 + c0    ];
                float a2 = As[(r0    ) * 36 + c0 + 4];
                float a3 = As[(r0 + 8) * 36 + c0 + 4];
                ah[im][0] = f2tf32(a0); al[im][0] = f2tf32(a0 - __uint_as_float(ah[im][0]));
                ah[im][1] = f2tf32(a1); al[im][1] = f2tf32(a1 - __uint_as_float(ah[im][1]));
                ah[im][2] = f2tf32(a2); al[im][2] = f2tf32(a2 - __uint_as_float(ah[im][2]));
                ah[im][3] = f2tf32(a3); al[im][3] = f2tf32(a3 - __uint_as_float(ah[im][3]));
            }
            // B fragments: rows ks*8 + {l%4, l%4+4}, col warpN*32 + in*8 + l/4
            uint32_t bh[4][2], bl[4][2];
#pragma unroll
            for (int in_ = 0; in_ < 4; in_++) {
                const int cc = warpN * 32 + in_ * 8 + (lane >> 2);
                float b0 = Bs[(ks * 8 + (lane & 3)    ) * 72 + cc];
                float b1 = Bs[(ks * 8 + (lane & 3) + 4) * 72 + cc];
                bh[in_][0] = f2tf32(b0); bl[in_][0] = f2tf32(b0 - __uint_as_float(bh[in_][0]));
                bh[in_][1] = f2tf32(b1); bl[in_][1] = f2tf32(b1 - __uint_as_float(bh[in_][1]));
            }
#pragma unroll
            for (int im = 0; im < 2; im++)
#pragma unroll
                for (int in_ = 0; in_ < 4; in_++) {
                    MMA_TF32(acc[im][in_], ah[im][0], ah[im][1], ah[im][2], ah[im][3],
                             bh[in_][0], bh[in_][1]);
                    MMA_TF32(acc[im][in_], al[im][0], al[im][1], al[im][2], al[im][3],
                             bh[in_][0], bh[in_][1]);
                    MMA_TF32(acc[im][in_], ah[im][0], ah[im][1], ah[im][2], ah[im][3],
                             bl[in_][0], bl[in_][1]);
                }
        }
        __syncthreads();
        if (t + 1 < T) {
#pragma unroll
            for (int i = 0; i < 4; i++)
                *(float4*)&As[aRow[i] * 36 + aC4 * 4] = pa[i];
#pragma unroll
            for (int i = 0; i < 2; i++)
                *(float4*)&Bs[bRow[i] * 72 + bC4 * 4] = pb[i];
            __syncthreads();
        }
    }

    // epilogue
#pragma unroll
    for (int im = 0; im < 2; im++)
#pragma unroll
        for (int in_ = 0; in_ < 4; in_++) {
            const int row = bm + warpM * 32 + im * 16 + (lane >> 2);
            const int col = bn + warpN * 32 + in_ * 8 + 2 * (lane & 3);
            float2 bb = *(const float2*)(bias + col);
            float v0 = acc[im][in_][0] + bb.x;
            float v1 = acc[im][in_][1] + bb.y;
            float v2 = acc[im][in_][2] + bb.x;
            float v3 = acc[im][in_][3] + bb.y;
            if (RELU) {
                v0 = fmaxf(v0, 0.f); v1 = fmaxf(v1, 0.f);
                v2 = fmaxf(v2, 0.f); v3 = fmaxf(v3, 0.f);
            }
            float2 o0; o0.x = v0; o0.y = v1;
            float2 o1; o1.x = v2; o1.y = v3;
            *(float2*)(C + (size_t)row * Nd + col)       = o0;
            *(float2*)(C + (size_t)(row + 8) * Nd + col) = o1;
        }
}

// ---------------- attention with smem window ----------------
// Ring graph: nodes [g*32, g*32+32) only reference k/v rows (g*32+1 .. g*32+63)
// mod N. One block per (node group, head): stage the 63-row k/v window + q in
// smem, then all the gather traffic hits shared memory (16x L1 reuse).
__global__ __launch_bounds__(256)
void attn_kernel(const float* __restrict__ q, const float* __restrict__ k,
                 const float* __restrict__ v, const void* __restrict__ ei,
                 const float* __restrict__ edge_attr,
                 const float* __restrict__ We, const float* __restrict__ be,
                 float* __restrict__ out)
{
    __shared__ __align__(16) float kS[63 * 65 + 1];   // pad 65: conflict-free rows
    __shared__ __align__(16) float vS[63 * 64];
    __shared__ __align__(16) float qS[32 * 64];
    __shared__ __align__(16) float WeS[64];

    const int g    = blockIdx.x;
    const int h    = blockIdx.y;
    const int base = g * 32;
    const int tid  = threadIdx.x;
    const int lane = tid & 31;
    const int wid  = tid >> 5;

    // stage window
    for (int idx = tid; idx < 63 * 16; idx += 256) {
        const int w = idx >> 4, c = idx & 15;
        int row = base + 1 + w; if (row >= NN) row -= NN;
        float4 kf = *(const float4*)(k + (size_t)row * HID + h * DD + c * 4);
        float4 vf = *(const float4*)(v + (size_t)row * HID + h * DD + c * 4);
        kS[w * 65 + c * 4 + 0] = kf.x; kS[w * 65 + c * 4 + 1] = kf.y;
        kS[w * 65 + c * 4 + 2] = kf.z; kS[w * 65 + c * 4 + 3] = kf.w;
        *(float4*)&vS[w * 64 + c * 4] = vf;
    }
    for (int idx = tid; idx < 32 * 16; idx += 256) {
        const int n = idx >> 4, c = idx & 15;
        *(float4*)&qS[n * 64 + c * 4] =
            *(const float4*)(q + (size_t)(base + n) * HID + h * DD + c * 4);
    }
    if (tid < 64) WeS[tid] = We[tid];
    __syncthreads();

    // edge_index dtype probe (int64 vs int32)
    const int probe = ((const int*)ei)[2 * EE - 1];
    const bool is64 = (probe == 0);
    const float beh = be[h];

    // each warp handles 4 nodes
    for (int s = 0; s < 4; s++) {
        const int nloc = wid * 4 + s;
        const int n    = base + nloc;
        const int e    = n * DEG + lane;

        int dst;
        if (is64) dst = (int)((const long long*)ei)[EE + e];
        else      dst = ((const int*)ei)[EE + e];
        int r = dst - base - 1; if (r < 0) r += NN;   // in [0,62]

        // edge bias
        float eb = beh;
        const float* ea = edge_attr + (size_t)e * 16;
        float4 e0 = *(const float4*)(ea);
        float4 e1 = *(const float4*)(ea + 4);
        float4 e2 = *(const float4*)(ea + 8);
        float4 e3 = *(const float4*)(ea + 12);
        eb = fmaf(e0.x, WeS[ 0 * NH + h], eb); eb = fmaf(e0.y, WeS[ 1 * NH + h], eb);
        eb = fmaf(e0.z, WeS[ 2 * NH + h], eb); eb = fmaf(e0.w, WeS[ 3 * NH + h], eb);
        eb = fmaf(e1.x, WeS[ 4 * NH + h], eb); eb = fmaf(e1.y, WeS[ 5 * NH + h], eb);
        eb = fmaf(e1.z, WeS[ 6 * NH + h], eb); eb = fmaf(e1.w, WeS[ 7 * NH + h], eb);
        eb = fmaf(e2.x, WeS[ 8 * NH + h], eb); eb = fmaf(e2.y, WeS[ 9 * NH + h], eb);
        eb = fmaf(e2.z, WeS[10 * NH + h], eb); eb = fmaf(e2.w, WeS[11 * NH + h], eb);
        eb = fmaf(e3.x, WeS[12 * NH + h], eb); eb = fmaf(e3.y, WeS[13 * NH + h], eb);
        eb = fmaf(e3.z, WeS[14 * NH + h], eb); eb = fmaf(e3.w, WeS[15 * NH + h], eb);

        // q . k  (q broadcast from smem, k per-lane row, conflict-free)
        const float* kr = kS + r * 65;
        const float* qr = qS + nloc * 64;
        float dotv = 0.f;
#pragma unroll
        for (int d = 0; d < DD; d += 4) {
            dotv = fmaf(qr[d    ], kr[d    ], dotv);
            dotv = fmaf(qr[d + 1], kr[d + 1], dotv);
            dotv = fmaf(qr[d + 2], kr[d + 2], dotv);
            dotv = fmaf(qr[d + 3], kr[d + 3], dotv);
        }
        float logit = dotv * 0.125f + eb;

        // warp softmax
        float m = logit;
#pragma unroll
        for (int o = 16; o; o >>= 1) m = fmaxf(m, __shfl_xor_sync(0xffffffffu, m, o));
        float p = __expf(logit - m);
        float ssum = p;
#pragma unroll
        for (int o = 16; o; o >>= 1) ssum += __shfl_xor_sync(0xffffffffu, ssum, o);
        const float prob = p / ssum;

        // weighted sum over v (lane owns 2 d-elements)
        float accx = 0.f, accy = 0.f;
#pragma unroll 8
        for (int j = 0; j < DEG; j++) {
            const int   rj = __shfl_sync(0xffffffffu, r,    j);
            const float pj = __shfl_sync(0xffffffffu, prob, j);
            float2 vf = *(float2*)&vS[rj * 64 + lane * 2];
            accx = fmaf(pj, vf.x, accx);
            accy = fmaf(pj, vf.y, accy);
        }
        float2 o2; o2.x = accx; o2.y = accy;
        *(float2*)(out + (size_t)n * HID + h * DD + lane * 2) = o2;
    }
}

// ---------------- residual + LayerNorm: one block (256 thr) per row -------
__global__ __launch_bounds__(256)
void ln_kernel(const float* __restrict__ x, const float* __restrict__ res,
               const float* __restrict__ g, const float* __restrict__ b,
               float* __restrict__ out)
{
    const int row = blockIdx.x;
    const int t   = threadIdx.x;

    const float val = x[(size_t)row * HID + t] + res[(size_t)row * HID + t];

    __shared__ __align__(16) float red[16];
    float s  = val;
    float q2 = val * val;
#pragma unroll
    for (int o = 16; o; o >>= 1) {
        s  += __shfl_xor_sync(0xffffffffu, s,  o);
        q2 += __shfl_xor_sync(0xffffffffu, q2, o);
    }
    const int w = t >> 5, l = t & 31;
    if (l == 0) { red[w] = s; red[8 + w] = q2; }
    __syncthreads();

    float ts = 0.f, tq = 0.f;
#pragma unroll
    for (int i = 0; i < 8; i++) { ts += red[i]; tq += red[8 + i]; }

    const float mean = ts * (1.f / HID);
    const float var  = tq * (1.f / HID) - mean * mean;
    const float r    = rsqrtf(var + 1e-5f);

    out[(size_t)row * HID + t] = (val - mean) * r * g[t] + b[t];
}

// ---------------- launch ----------------
extern "C" void kernel_launch(void* const* d_in, const int* in_sizes, int n_in,
                              void* d_out, int out_size)
{
    const float* x   = (const float*)d_in[0];
    const void*  ei  = d_in[1];
    const float* ea  = (const float*)d_in[2];
    const float* Wq  = (const float*)d_in[3];
    const float* bq  = (const float*)d_in[4];
    const float* Wk  = (const float*)d_in[5];
    const float* bk  = (const float*)d_in[6];
    const float* Wv  = (const float*)d_in[7];
    const float* bv  = (const float*)d_in[8];
    const float* Wo  = (const float*)d_in[9];
    const float* bo  = (const float*)d_in[10];
    const float* We  = (const float*)d_in[11];
    const float* be  = (const float*)d_in[12];
    const float* g1  = (const float*)d_in[13];
    const float* b1  = (const float*)d_in[14];
    const float* g2  = (const float*)d_in[15];
    const float* b2  = (const float*)d_in[16];
    const float* Wf1 = (const float*)d_in[17];
    const float* bf1 = (const float*)d_in[18];
    const float* Wf2 = (const float*)d_in[19];
    const float* bf2 = (const float*)d_in[20];
    float* out = (float*)d_out;

    float *q, *k, *v, *ao, *ot, *x1, *h1, *f2;
    cudaGetSymbolAddress((void**)&q,  g_q);
    cudaGetSymbolAddress((void**)&k,  g_k);
    cudaGetSymbolAddress((void**)&v,  g_v);
    cudaGetSymbolAddress((void**)&ao, g_ao);
    cudaGetSymbolAddress((void**)&ot, g_ot);
    cudaGetSymbolAddress((void**)&x1, g_x1);
    cudaGetSymbolAddress((void**)&h1, g_h1);
    cudaGetSymbolAddress((void**)&f2, g_f2);

    const dim3 gQKV(HID / 64, NN / 128);          // (4, 32)
    const dim3 gF1 (4 * HID / 64, NN / 128);      // (16, 32)
    const dim3 gF2 (HID / 64, NN / 128);          // (4, 32)

    gemm_tf32<false><<<gQKV, 256>>>(x, Wq, bq, q, NN, HID, HID);
    gemm_tf32<false><<<gQKV, 256>>>(x, Wk, bk, k, NN, HID, HID);
    gemm_tf32<false><<<gQKV, 256>>>(x, Wv, bv, v, NN, HID, HID);

    attn_kernel<<<dim3(NN / 32, NH), 256>>>(q, k, v, ei, ea, We, be, ao);

    gemm_tf32<false><<<gQKV, 256>>>(ao, Wo, bo, ot, NN, HID, HID);

    ln_kernel<<<NN, HID>>>(x, ot, g1, b1, x1);

    gemm_tf32<true ><<<gF1, 256>>>(x1, Wf1, bf1, h1, NN, HID, 4 * HID);
    gemm_tf32<false><<<gF2, 256>>>(h1, Wf2, bf2, f2, NN, 4 * HID, HID);

    ln_kernel<<<NN, HID>>>(x1, f2, g2, b2, out);
}

// round 7
// speedup vs baseline: 2.1335x; 1.2193x over previous
#include <cuda_runtime.h>
#include <cuda_bf16.h>
#include <math.h>
#include <stdint.h>

// ---------------- problem constants ----------------
#define NN   4096
#define HID  256
#define NH   4
#define DD   64
#define DEG  32
#define EE   (NN * DEG)

// ---------------- scratch (device globals; no allocation) ----------------
__device__ float g_q [NN * HID];
__device__ float g_k [NN * HID];
__device__ float g_v [NN * HID];
__device__ float g_ao[NN * HID];     // attention output (pre-Wo)
__device__ float g_ot[NN * HID];     // Wo output
__device__ float g_x1[NN * HID];     // after first LN
__device__ float g_h1[NN * 4 * HID]; // FFN hidden
__device__ float g_f2[NN * HID];     // FFN output

// ---------------- helpers ----------------
__device__ __forceinline__ uint32_t pk(__nv_bfloat16 a, __nv_bfloat16 b) {
    // low half = a (lower k index), high half = b
    uint16_t ua = *(uint16_t*)&a, ub = *(uint16_t*)&b;
    return (uint32_t)ua | ((uint32_t)ub << 16);
}
__device__ __forceinline__ void split_bf16(float x, __nv_bfloat16& h, __nv_bfloat16& l) {
    h = __float2bfloat16(x);
    l = __float2bfloat16(x - __bfloat162float(h));
}

#define MMA_BF16(d, a0, a1, a2, a3, b0, b1)                                   \
    asm volatile(                                                             \
        "mma.sync.aligned.m16n8k16.row.col.f32.bf16.bf16.f32 "                \
        "{%0,%1,%2,%3},{%4,%5,%6,%7},{%8,%9},{%0,%1,%2,%3};"                  \
        : "+f"(d[0]), "+f"(d[1]), "+f"(d[2]), "+f"(d[3])                      \
        : "r"(a0), "r"(a1), "r"(a2), "r"(a3), "r"(b0), "r"(b1))

// ---------------- bf16-split tensor-core GEMM ----------------
// C[M,N] = A[M,K] @ B[K,N] + bias (+ReLU). BM=128, BN=64, BK=32.
// fp32 split into hi/lo bf16 at staging; 3-product scheme per k16 chunk:
// acc += Ah*Bh + Al*Bh + Ah*Bl   (error ~2^-16, plenty under 1e-3 gate).
// 256 threads = 8 warps (4M x 2N); warp tile 32x32 = 2x4 m16n8k16 MMAs.
template <bool RELU>
__global__ __launch_bounds__(256)
void gemm_bf16(const float* __restrict__ A, const float* __restrict__ B,
               const float* __restrict__ bias, float* __restrict__ C,
               int M, int K, int Nd)
{
    // A: [row][k] bf16, row stride 40 (pad) -> conflict-free frag loads
    __shared__ __align__(16) __nv_bfloat16 Ah[128 * 40];
    __shared__ __align__(16) __nv_bfloat16 Al[128 * 40];
    // B: k-pairs packed as uint32 [pair p][col n], stride 72 -> bank 8p+c
    __shared__ __align__(16) uint32_t Bh[16 * 72];
    __shared__ __align__(16) uint32_t Bl[16 * 72];

    const int tid   = threadIdx.x;
    const int lane  = tid & 31;
    const int wid   = tid >> 5;
    const int warpM = wid >> 1;      // 0..3
    const int warpN = wid & 1;       // 0..1
    const int bm    = blockIdx.y * 128;
    const int bn    = blockIdx.x * 64;

    // gmem load mappings (A tile 128x32: 4 float4/thread; B tile 32x64: 2)
    const int aRow[4] = { (tid + 0*256) >> 3, (tid + 1*256) >> 3,
                          (tid + 2*256) >> 3, (tid + 3*256) >> 3 };
    const int aC4 = tid & 7;
    const int bRow[2] = { (tid + 0*256) >> 4, (tid + 1*256) >> 4 };
    const int bC4 = tid & 15;

    float acc[2][4][4];
#pragma unroll
    for (int i = 0; i < 2; i++)
#pragma unroll
        for (int j = 0; j < 4; j++)
#pragma unroll
            for (int r = 0; r < 4; r++) acc[i][j][r] = 0.f;

    const int T = K >> 5;
    float4 pa[4], pb[2];

    // prefetch tile 0
#pragma unroll
    for (int i = 0; i < 4; i++)
        pa[i] = *(const float4*)(A + (size_t)(bm + aRow[i]) * K + aC4 * 4);
#pragma unroll
    for (int i = 0; i < 2; i++)
        pb[i] = *(const float4*)(B + (size_t)bRow[i] * Nd + bn + bC4 * 4);

    // stage tile 0
    {
#pragma unroll
        for (int i = 0; i < 4; i++) {
            __nv_bfloat16 h0,h1,h2,h3,l0,l1,l2,l3;
            split_bf16(pa[i].x, h0, l0); split_bf16(pa[i].y, h1, l1);
            split_bf16(pa[i].z, h2, l2); split_bf16(pa[i].w, h3, l3);
            uint2 uh; uh.x = pk(h0,h1); uh.y = pk(h2,h3);
            uint2 ul; ul.x = pk(l0,l1); ul.y = pk(l2,l3);
            *(uint2*)&Ah[aRow[i] * 40 + aC4 * 4] = uh;
            *(uint2*)&Al[aRow[i] * 40 + aC4 * 4] = ul;
        }
        __nv_bfloat16* BH = (__nv_bfloat16*)Bh;
        __nv_bfloat16* BL = (__nv_bfloat16*)Bl;
#pragma unroll
        for (int i = 0; i < 2; i++) {
            const int kk = bRow[i];
            const int p  = kk >> 1, hf = kk & 1;
            __nv_bfloat16 h, l;
            const float bb[4] = { pb[i].x, pb[i].y, pb[i].z, pb[i].w };
#pragma unroll
            for (int j = 0; j < 4; j++) {
                split_bf16(bb[j], h, l);
                const int n = bC4 * 4 + j;
                BH[(p * 72 + n) * 2 + hf] = h;
                BL[(p * 72 + n) * 2 + hf] = l;
            }
        }
    }
    __syncthreads();

    for (int t = 0; t < T; t++) {
        if (t + 1 < T) {
            const int k0 = (t + 1) << 5;
#pragma unroll
            for (int i = 0; i < 4; i++)
                pa[i] = *(const float4*)(A + (size_t)(bm + aRow[i]) * K + k0 + aC4 * 4);
#pragma unroll
            for (int i = 0; i < 2; i++)
                pb[i] = *(const float4*)(B + (size_t)(k0 + bRow[i]) * Nd + bn + bC4 * 4);
        }

#pragma unroll
        for (int kc = 0; kc < 2; kc++) {
            const int kb = kc * 16 + 2 * (lane & 3);
            uint32_t ahr[2][4], alr[2][4];
#pragma unroll
            for (int im = 0; im < 2; im++) {
                const int r0 = warpM * 32 + im * 16 + (lane >> 2);
                ahr[im][0] = *(uint32_t*)&Ah[(r0    ) * 40 + kb    ];
                ahr[im][1] = *(uint32_t*)&Ah[(r0 + 8) * 40 + kb    ];
                ahr[im][2] = *(uint32_t*)&Ah[(r0    ) * 40 + kb + 8];
                ahr[im][3] = *(uint32_t*)&Ah[(r0 + 8) * 40 + kb + 8];
                alr[im][0] = *(uint32_t*)&Al[(r0    ) * 40 + kb    ];
                alr[im][1] = *(uint32_t*)&Al[(r0 + 8) * 40 + kb    ];
                alr[im][2] = *(uint32_t*)&Al[(r0    ) * 40 + kb + 8];
                alr[im][3] = *(uint32_t*)&Al[(r0 + 8) * 40 + kb + 8];
            }
            uint32_t bhr[4][2], blr[4][2];
            const int p0 = kc * 8 + (lane & 3);
#pragma unroll
            for (int in_ = 0; in_ < 4; in_++) {
                const int c = warpN * 32 + in_ * 8 + (lane >> 2);
                bhr[in_][0] = Bh[(p0    ) * 72 + c];
                bhr[in_][1] = Bh[(p0 + 4) * 72 + c];
                blr[in_][0] = Bl[(p0    ) * 72 + c];
                blr[in_][1] = Bl[(p0 + 4) * 72 + c];
            }
#pragma unroll
            for (int im = 0; im < 2; im++)
#pragma unroll
                for (int in_ = 0; in_ < 4; in_++) {
                    MMA_BF16(acc[im][in_], ahr[im][0], ahr[im][1], ahr[im][2], ahr[im][3],
                             bhr[in_][0], bhr[in_][1]);
                    MMA_BF16(acc[im][in_], alr[im][0], alr[im][1], alr[im][2], alr[im][3],
                             bhr[in_][0], bhr[in_][1]);
                    MMA_BF16(acc[im][in_], ahr[im][0], ahr[im][1], ahr[im][2], ahr[im][3],
                             blr[in_][0], blr[in_][1]);
                }
        }
        __syncthreads();
        if (t + 1 < T) {
#pragma unroll
            for (int i = 0; i < 4; i++) {
                __nv_bfloat16 h0,h1,h2,h3,l0,l1,l2,l3;
                split_bf16(pa[i].x, h0, l0); split_bf16(pa[i].y, h1, l1);
                split_bf16(pa[i].z, h2, l2); split_bf16(pa[i].w, h3, l3);
                uint2 uh; uh.x = pk(h0,h1); uh.y = pk(h2,h3);
                uint2 ul; ul.x = pk(l0,l1); ul.y = pk(l2,l3);
                *(uint2*)&Ah[aRow[i] * 40 + aC4 * 4] = uh;
                *(uint2*)&Al[aRow[i] * 40 + aC4 * 4] = ul;
            }
            __nv_bfloat16* BH = (__nv_bfloat16*)Bh;
            __nv_bfloat16* BL = (__nv_bfloat16*)Bl;
#pragma unroll
            for (int i = 0; i < 2; i++) {
                const int kk = bRow[i];
                const int p  = kk >> 1, hf = kk & 1;
                __nv_bfloat16 h, l;
                const float bb[4] = { pb[i].x, pb[i].y, pb[i].z, pb[i].w };
#pragma unroll
                for (int j = 0; j < 4; j++) {
                    split_bf16(bb[j], h, l);
                    const int n = bC4 * 4 + j;
                    BH[(p * 72 + n) * 2 + hf] = h;
                    BL[(p * 72 + n) * 2 + hf] = l;
                }
            }
            __syncthreads();
        }
    }

    // epilogue (same accumulator layout as m16n8 tf32)
#pragma unroll
    for (int im = 0; im < 2; im++)
#pragma unroll
        for (int in_ = 0; in_ < 4; in_++) {
            const int row = bm + warpM * 32 + im * 16 + (lane >> 2);
            const int col = bn + warpN * 32 + in_ * 8 + 2 * (lane & 3);
            float2 bb = *(const float2*)(bias + col);
            float v0 = acc[im][in_][0] + bb.x;
            float v1 = acc[im][in_][1] + bb.y;
            float v2 = acc[im][in_][2] + bb.x;
            float v3 = acc[im][in_][3] + bb.y;
            if (RELU) {
                v0 = fmaxf(v0, 0.f); v1 = fmaxf(v1, 0.f);
                v2 = fmaxf(v2, 0.f); v3 = fmaxf(v3, 0.f);
            }
            float2 o0; o0.x = v0; o0.y = v1;
            float2 o1; o1.x = v2; o1.y = v3;
            *(float2*)(C + (size_t)row * Nd + col)       = o0;
            *(float2*)(C + (size_t)(row + 8) * Nd + col) = o1;
        }
}

// ---------------- attention with smem window ----------------
// Ring graph: nodes [g*32, g*32+32) reference k/v rows (g*32+1 .. g*32+63) mod N.
// 512 threads; block per (group, head). No shfl chains: (r, prob) broadcast via smem.
__global__ __launch_bounds__(512)
void attn_kernel(const float* __restrict__ q, const float* __restrict__ k,
                 const float* __restrict__ v, const void* __restrict__ ei,
                 const float* __restrict__ edge_attr,
                 const float* __restrict__ We, const float* __restrict__ be,
                 float* __restrict__ out)
{
    __shared__ __align__(16) float kS[63 * 65 + 3];  // stride 65: conflict-free rows
    __shared__ __align__(16) float vS[63 * 64];
    __shared__ __align__(16) float qS[32 * 64];
    __shared__ __align__(16) float WeS[64];
    __shared__ __align__(16) int   rS[16][32];
    __shared__ __align__(16) float pS[16][32];

    const int g    = blockIdx.x;
    const int h    = blockIdx.y;
    const int base = g * 32;
    const int tid  = threadIdx.x;
    const int lane = tid & 31;
    const int wid  = tid >> 5;    // 0..15

    // stage window
    for (int idx = tid; idx < 63 * 16; idx += 512) {
        const int w = idx >> 4, c = idx & 15;
        int row = base + 1 + w; if (row >= NN) row -= NN;
        float4 kf = *(const float4*)(k + (size_t)row * HID + h * DD + c * 4);
        float4 vf = *(const float4*)(v + (size_t)row * HID + h * DD + c * 4);
        kS[w * 65 + c * 4 + 0] = kf.x; kS[w * 65 + c * 4 + 1] = kf.y;
        kS[w * 65 + c * 4 + 2] = kf.z; kS[w * 65 + c * 4 + 3] = kf.w;
        *(float4*)&vS[w * 64 + c * 4] = vf;
    }
    for (int idx = tid; idx < 32 * 16; idx += 512) {
        const int n = idx >> 4, c = idx & 15;
        *(float4*)&qS[n * 64 + c * 4] =
            *(const float4*)(q + (size_t)(base + n) * HID + h * DD + c * 4);
    }
    if (tid < 64) WeS[tid] = We[tid];
    __syncthreads();

    // edge_index dtype probe (int64 vs int32)
    const int probe = ((const int*)ei)[2 * EE - 1];
    const bool is64 = (probe == 0);
    const float beh = be[h];

    // each warp handles 2 nodes
#pragma unroll
    for (int s = 0; s < 2; s++) {
        const int nloc = wid * 2 + s;
        const int n    = base + nloc;
        const int e    = n * DEG + lane;

        int dst;
        if (is64) dst = (int)((const long long*)ei)[EE + e];
        else      dst = ((const int*)ei)[EE + e];
        int r = dst - base - 1; if (r < 0) r += NN;   // in [0,62]

        // edge bias
        float eb = beh;
        const float* ea = edge_attr + (size_t)e * 16;
        float4 e0 = *(const float4*)(ea);
        float4 e1 = *(const float4*)(ea + 4);
        float4 e2 = *(const float4*)(ea + 8);
        float4 e3 = *(const float4*)(ea + 12);
        eb = fmaf(e0.x, WeS[ 0 * NH + h], eb); eb = fmaf(e0.y, WeS[ 1 * NH + h], eb);
        eb = fmaf(e0.z, WeS[ 2 * NH + h], eb); eb = fmaf(e0.w, WeS[ 3 * NH + h], eb);
        eb = fmaf(e1.x, WeS[ 4 * NH + h], eb); eb = fmaf(e1.y, WeS[ 5 * NH + h], eb);
        eb = fmaf(e1.z, WeS[ 6 * NH + h], eb); eb = fmaf(e1.w, WeS[ 7 * NH + h], eb);
        eb = fmaf(e2.x, WeS[ 8 * NH + h], eb); eb = fmaf(e2.y, WeS[ 9 * NH + h], eb);
        eb = fmaf(e2.z, WeS[10 * NH + h], eb); eb = fmaf(e2.w, WeS[11 * NH + h], eb);
        eb = fmaf(e3.x, WeS[12 * NH + h], eb); eb = fmaf(e3.y, WeS[13 * NH + h], eb);
        eb = fmaf(e3.z, WeS[14 * NH + h], eb); eb = fmaf(e3.w, WeS[15 * NH + h], eb);

        // q . k  (q broadcast, k per-lane row; two chains for ILP)
        const float* kr = kS + r * 65;
        const float* qr = qS + nloc * 64;
        float d0 = 0.f, d1 = 0.f;
#pragma unroll
        for (int d = 0; d < DD; d += 4) {
            d0 = fmaf(qr[d    ], kr[d    ], d0);
            d1 = fmaf(qr[d + 1], kr[d + 1], d1);
            d0 = fmaf(qr[d + 2], kr[d + 2], d0);
            d1 = fmaf(qr[d + 3], kr[d + 3], d1);
        }
        float logit = (d0 + d1) * 0.125f + eb;

        // warp softmax (reductions only -> log2 shfls, fine)
        float m = logit;
#pragma unroll
        for (int o = 16; o; o >>= 1) m = fmaxf(m, __shfl_xor_sync(0xffffffffu, m, o));
        float p = __expf(logit - m);
        float ssum = p;
#pragma unroll
        for (int o = 16; o; o >>= 1) ssum += __shfl_xor_sync(0xffffffffu, ssum, o);
        const float prob = p / ssum;

        // broadcast (r, prob) through smem; no shfl in the hot loop
        rS[wid][lane] = r;
        pS[wid][lane] = prob;
        __syncwarp();

        float accx = 0.f, accy = 0.f;
#pragma unroll 8
        for (int j = 0; j < DEG; j++) {
            const int   rj = rS[wid][j];
            const float pj = pS[wid][j];
            float2 vf = *(float2*)&vS[rj * 64 + lane * 2];
            accx = fmaf(pj, vf.x, accx);
            accy = fmaf(pj, vf.y, accy);
        }
        float2 o2; o2.x = accx; o2.y = accy;
        *(float2*)(out + (size_t)n * HID + h * DD + lane * 2) = o2;
        __syncwarp();
    }
}

// ---------------- residual + LayerNorm: one block (256 thr) per row -------
__global__ __launch_bounds__(256)
void ln_kernel(const float* __restrict__ x, const float* __restrict__ res,
               const float* __restrict__ g, const float* __restrict__ b,
               float* __restrict__ out)
{
    const int row = blockIdx.x;
    const int t   = threadIdx.x;

    const float val = x[(size_t)row * HID + t] + res[(size_t)row * HID + t];

    __shared__ __align__(16) float red[16];
    float s  = val;
    float q2 = val * val;
#pragma unroll
    for (int o = 16; o; o >>= 1) {
        s  += __shfl_xor_sync(0xffffffffu, s,  o);
        q2 += __shfl_xor_sync(0xffffffffu, q2, o);
    }
    const int w = t >> 5, l = t & 31;
    if (l == 0) { red[w] = s; red[8 + w] = q2; }
    __syncthreads();

    float ts = 0.f, tq = 0.f;
#pragma unroll
    for (int i = 0; i < 8; i++) { ts += red[i]; tq += red[8 + i]; }

    const float mean = ts * (1.f / HID);
    const float var  = tq * (1.f / HID) - mean * mean;
    const float r    = rsqrtf(var + 1e-5f);

    out[(size_t)row * HID + t] = (val - mean) * r * g[t] + b[t];
}

// ---------------- launch ----------------
extern "C" void kernel_launch(void* const* d_in, const int* in_sizes, int n_in,
                              void* d_out, int out_size)
{
    const float* x   = (const float*)d_in[0];
    const void*  ei  = d_in[1];
    const float* ea  = (const float*)d_in[2];
    const float* Wq  = (const float*)d_in[3];
    const float* bq  = (const float*)d_in[4];
    const float* Wk  = (const float*)d_in[5];
    const float* bk  = (const float*)d_in[6];
    const float* Wv  = (const float*)d_in[7];
    const float* bv  = (const float*)d_in[8];
    const float* Wo  = (const float*)d_in[9];
    const float* bo  = (const float*)d_in[10];
    const float* We  = (const float*)d_in[11];
    const float* be  = (const float*)d_in[12];
    const float* g1  = (const float*)d_in[13];
    const float* b1  = (const float*)d_in[14];
    const float* g2  = (const float*)d_in[15];
    const float* b2  = (const float*)d_in[16];
    const float* Wf1 = (const float*)d_in[17];
    const float* bf1 = (const float*)d_in[18];
    const float* Wf2 = (const float*)d_in[19];
    const float* bf2 = (const float*)d_in[20];
    float* out = (float*)d_out;

    float *q, *k, *v, *ao, *ot, *x1, *h1, *f2;
    cudaGetSymbolAddress((void**)&q,  g_q);
    cudaGetSymbolAddress((void**)&k,  g_k);
    cudaGetSymbolAddress((void**)&v,  g_v);
    cudaGetSymbolAddress((void**)&ao, g_ao);
    cudaGetSymbolAddress((void**)&ot, g_ot);
    cudaGetSymbolAddress((void**)&x1, g_x1);
    cudaGetSymbolAddress((void**)&h1, g_h1);
    cudaGetSymbolAddress((void**)&f2, g_f2);

    const dim3 gQKV(HID / 64, NN / 128);          // (4, 32)
    const dim3 gF1 (4 * HID / 64, NN / 128);      // (16, 32)
    const dim3 gF2 (HID / 64, NN / 128);          // (4, 32)

    gemm_bf16<false><<<gQKV, 256>>>(x, Wq, bq, q, NN, HID, HID);
    gemm_bf16<false><<<gQKV, 256>>>(x, Wk, bk, k, NN, HID, HID);
    gemm_bf16<false><<<gQKV, 256>>>(x, Wv, bv, v, NN, HID, HID);

    attn_kernel<<<dim3(NN / 32, NH), 512>>>(q, k, v, ei, ea, We, be, ao);

    gemm_bf16<false><<<gQKV, 256>>>(ao, Wo, bo, ot, NN, HID, HID);

    ln_kernel<<<NN, HID>>>(x, ot, g1, b1, x1);

    gemm_bf16<true ><<<gF1, 256>>>(x1, Wf1, bf1, h1, NN, HID, 4 * HID);
    gemm_bf16<false><<<gF2, 256>>>(h1, Wf2, bf2, f2, NN, 4 * HID, HID);

    ln_kernel<<<NN, HID>>>(x1, f2, g2, b2, out);
}

// round 8
// speedup vs baseline: 2.1654x; 1.0150x over previous
#include <cuda_runtime.h>
#include <cuda_bf16.h>
#include <math.h>
#include <stdint.h>

// ---------------- problem constants ----------------
#define NN   4096
#define HID  256
#define NH   4
#define DD   64
#define DEG  32
#define EE   (NN * DEG)
#define HID4 (4 * HID)

// ---------------- scratch (device globals; no allocation) ----------------
__device__ __nv_bfloat16 g_xh [NN * HID],  g_xl [NN * HID];
__device__ float         g_q  [NN * HID];
__device__ float         g_k  [NN * HID];
__device__ float         g_v  [NN * HID];
__device__ __nv_bfloat16 g_aoh[NN * HID],  g_aol[NN * HID];
__device__ float         g_ot [NN * HID];
__device__ float         g_x1 [NN * HID];
__device__ __nv_bfloat16 g_x1h[NN * HID],  g_x1l[NN * HID];
__device__ __nv_bfloat16 g_h1h[NN * HID4], g_h1l[NN * HID4];
__device__ float         g_f2 [NN * HID];
// packed weights: uint32 word = (bf16 @ k even, bf16 @ k odd), layout [K/2][N]
__device__ uint32_t g_wqh [HID/2  * HID],  g_wql [HID/2  * HID];
__device__ uint32_t g_wkh [HID/2  * HID],  g_wkl [HID/2  * HID];
__device__ uint32_t g_wvh [HID/2  * HID],  g_wvl [HID/2  * HID];
__device__ uint32_t g_woh [HID/2  * HID],  g_wol [HID/2  * HID];
__device__ uint32_t g_wf1h[HID/2  * HID4], g_wf1l[HID/2  * HID4];
__device__ uint32_t g_wf2h[HID4/2 * HID],  g_wf2l[HID4/2 * HID];

// ---------------- helpers ----------------
__device__ __forceinline__ uint32_t pk(__nv_bfloat16 a, __nv_bfloat16 b) {
    uint16_t ua = *(uint16_t*)&a, ub = *(uint16_t*)&b;
    return (uint32_t)ua | ((uint32_t)ub << 16);
}
__device__ __forceinline__ void split_bf16(float x, __nv_bfloat16& h, __nv_bfloat16& l) {
    h = __float2bfloat16(x);
    l = __float2bfloat16(x - __bfloat162float(h));
}

#define MMA_BF16(d, a0, a1, a2, a3, b0, b1)                                   \
    asm volatile(                                                             \
        "mma.sync.aligned.m16n8k16.row.col.f32.bf16.bf16.f32 "                \
        "{%0,%1,%2,%3},{%4,%5,%6,%7},{%8,%9},{%0,%1,%2,%3};"                  \
        : "+f"(d[0]), "+f"(d[1]), "+f"(d[2]), "+f"(d[3])                      \
        : "r"(a0), "r"(a1), "r"(a2), "r"(a3), "r"(b0), "r"(b1))

// ---------------- weight packing (once per launch; cheap) ----------------
__global__ void pack_w_kernel(const float* __restrict__ Wq, const float* __restrict__ Wk,
                              const float* __restrict__ Wv, const float* __restrict__ Wo,
                              const float* __restrict__ Wf1, const float* __restrict__ Wf2)
{
    const int z = blockIdx.z;
    const float* W; uint32_t* oh; uint32_t* ol; int K, N;
    switch (z) {
        case 0:  W = Wq;  oh = g_wqh;  ol = g_wql;  K = HID;  N = HID;  break;
        case 1:  W = Wk;  oh = g_wkh;  ol = g_wkl;  K = HID;  N = HID;  break;
        case 2:  W = Wv;  oh = g_wvh;  ol = g_wvl;  K = HID;  N = HID;  break;
        case 3:  W = Wo;  oh = g_woh;  ol = g_wol;  K = HID;  N = HID;  break;
        case 4:  W = Wf1; oh = g_wf1h; ol = g_wf1l; K = HID;  N = HID4; break;
        default: W = Wf2; oh = g_wf2h; ol = g_wf2l; K = HID4; N = HID;  break;
    }
    const int total = (K / 2) * N;
    for (int i = blockIdx.x * blockDim.x + threadIdx.x; i < total;
         i += gridDim.x * blockDim.x) {
        const int p = i / N, n = i - p * N;
        const float a = W[(size_t)(2 * p) * N + n];
        const float b = W[(size_t)(2 * p + 1) * N + n];
        __nv_bfloat16 ah, al, bh, bl;
        split_bf16(a, ah, al);
        split_bf16(b, bh, bl);
        oh[i] = pk(ah, bh);
        ol[i] = pk(al, bl);
    }
}

// ---------------- elementwise fp32 -> bf16 hi/lo split ----------------
__global__ void split_x_kernel(const float* __restrict__ in,
                               __nv_bfloat16* __restrict__ oh,
                               __nv_bfloat16* __restrict__ ol, int n4)
{
    const int i = blockIdx.x * blockDim.x + threadIdx.x;
    if (i >= n4) return;
    float4 v = ((const float4*)in)[i];
    __nv_bfloat16 h0,h1,h2,h3,l0,l1,l2,l3;
    split_bf16(v.x, h0, l0); split_bf16(v.y, h1, l1);
    split_bf16(v.z, h2, l2); split_bf16(v.w, h3, l3);
    uint2 uh; uh.x = pk(h0, h1); uh.y = pk(h2, h3);
    uint2 ul; ul.x = pk(l0, l1); ul.y = pk(l2, l3);
    ((uint2*)oh)[i] = uh;
    ((uint2*)ol)[i] = ul;
}

// ---------------- pre-packed bf16-split GEMM ----------------
// C = A @ B + bias. A: bf16 hi/lo [M][K]; B: packed uint32 hi/lo [K/2][N].
// 3-product: Ah*Bh + Al*Bh + Ah*Bl. BM=128,BN=64,BK=32; 8 warps (4Mx2N).
// EPI 0: fp32 C. EPI 1: relu + bf16 hi/lo split to Ch/Cl.
template <int EPI>
__global__ __launch_bounds__(256)
void gemm_pk(const __nv_bfloat16* __restrict__ Agh, const __nv_bfloat16* __restrict__ Agl,
             const uint32_t* __restrict__ Bgh, const uint32_t* __restrict__ Bgl,
             const float* __restrict__ bias,
             float* __restrict__ C,
             __nv_bfloat16* __restrict__ Ch, __nv_bfloat16* __restrict__ Cl,
             int M, int K, int Nd)
{
    __shared__ __align__(16) __nv_bfloat16 Ah[128 * 40];
    __shared__ __align__(16) __nv_bfloat16 Al[128 * 40];
    __shared__ __align__(16) uint32_t Bh[16 * 72];
    __shared__ __align__(16) uint32_t Bl[16 * 72];

    const int tid   = threadIdx.x;
    const int lane  = tid & 31;
    const int wid   = tid >> 5;
    const int warpM = wid >> 1;
    const int warpN = wid & 1;
    const int bm    = blockIdx.y * 128;
    const int bn    = blockIdx.x * 64;

    // staging mappings: A = 2 uint4 (8 bf16 each) per array; B = 1 uint4 (4 words)
    const int aRow0 = tid >> 2;
    const int aRow1 = (tid + 256) >> 2;
    const int aK    = (tid & 3) * 8;
    const int bP    = tid >> 4;
    const int bN4   = (tid & 15) * 4;

    float acc[2][4][4];
#pragma unroll
    for (int i = 0; i < 2; i++)
#pragma unroll
        for (int j = 0; j < 4; j++)
#pragma unroll
            for (int r = 0; r < 4; r++) acc[i][j][r] = 0.f;

    const int T = K >> 5;
    uint4 ph0, ph1, pl0, pl1, qh, ql;

    // prefetch tile 0
    ph0 = *(const uint4*)(Agh + (size_t)(bm + aRow0) * K + aK);
    ph1 = *(const uint4*)(Agh + (size_t)(bm + aRow1) * K + aK);
    pl0 = *(const uint4*)(Agl + (size_t)(bm + aRow0) * K + aK);
    pl1 = *(const uint4*)(Agl + (size_t)(bm + aRow1) * K + aK);
    qh  = *(const uint4*)(Bgh + (size_t)bP * Nd + bn + bN4);
    ql  = *(const uint4*)(Bgl + (size_t)bP * Nd + bn + bN4);
    *(uint4*)&Ah[aRow0 * 40 + aK] = ph0;
    *(uint4*)&Ah[aRow1 * 40 + aK] = ph1;
    *(uint4*)&Al[aRow0 * 40 + aK] = pl0;
    *(uint4*)&Al[aRow1 * 40 + aK] = pl1;
    *(uint4*)&Bh[bP * 72 + bN4] = qh;
    *(uint4*)&Bl[bP * 72 + bN4] = ql;
    __syncthreads();

    for (int t = 0; t < T; t++) {
        if (t + 1 < T) {
            const int k0 = (t + 1) << 5;
            ph0 = *(const uint4*)(Agh + (size_t)(bm + aRow0) * K + k0 + aK);
            ph1 = *(const uint4*)(Agh + (size_t)(bm + aRow1) * K + k0 + aK);
            pl0 = *(const uint4*)(Agl + (size_t)(bm + aRow0) * K + k0 + aK);
            pl1 = *(const uint4*)(Agl + (size_t)(bm + aRow1) * K + k0 + aK);
            qh  = *(const uint4*)(Bgh + (size_t)((k0 >> 1) + bP) * Nd + bn + bN4);
            ql  = *(const uint4*)(Bgl + (size_t)((k0 >> 1) + bP) * Nd + bn + bN4);
        }

#pragma unroll
        for (int kc = 0; kc < 2; kc++) {
            const int kb = kc * 16 + 2 * (lane & 3);
            uint32_t ahr[2][4], alr[2][4];
#pragma unroll
            for (int im = 0; im < 2; im++) {
                const int r0 = warpM * 32 + im * 16 + (lane >> 2);
                ahr[im][0] = *(uint32_t*)&Ah[(r0    ) * 40 + kb    ];
                ahr[im][1] = *(uint32_t*)&Ah[(r0 + 8) * 40 + kb    ];
                ahr[im][2] = *(uint32_t*)&Ah[(r0    ) * 40 + kb + 8];
                ahr[im][3] = *(uint32_t*)&Ah[(r0 + 8) * 40 + kb + 8];
                alr[im][0] = *(uint32_t*)&Al[(r0    ) * 40 + kb    ];
                alr[im][1] = *(uint32_t*)&Al[(r0 + 8) * 40 + kb    ];
                alr[im][2] = *(uint32_t*)&Al[(r0    ) * 40 + kb + 8];
                alr[im][3] = *(uint32_t*)&Al[(r0 + 8) * 40 + kb + 8];
            }
            uint32_t bhr[4][2], blr[4][2];
            const int p0 = kc * 8 + (lane & 3);
#pragma unroll
            for (int in_ = 0; in_ < 4; in_++) {
                const int c = warpN * 32 + in_ * 8 + (lane >> 2);
                bhr[in_][0] = Bh[(p0    ) * 72 + c];
                bhr[in_][1] = Bh[(p0 + 4) * 72 + c];
                blr[in_][0] = Bl[(p0    ) * 72 + c];
                blr[in_][1] = Bl[(p0 + 4) * 72 + c];
            }
#pragma unroll
            for (int im = 0; im < 2; im++)
#pragma unroll
                for (int in_ = 0; in_ < 4; in_++) {
                    MMA_BF16(acc[im][in_], ahr[im][0], ahr[im][1], ahr[im][2], ahr[im][3],
                             bhr[in_][0], bhr[in_][1]);
                    MMA_BF16(acc[im][in_], alr[im][0], alr[im][1], alr[im][2], alr[im][3],
                             bhr[in_][0], bhr[in_][1]);
                    MMA_BF16(acc[im][in_], ahr[im][0], ahr[im][1], ahr[im][2], ahr[im][3],
                             blr[in_][0], blr[in_][1]);
                }
        }
        __syncthreads();
        if (t + 1 < T) {
            *(uint4*)&Ah[aRow0 * 40 + aK] = ph0;
            *(uint4*)&Ah[aRow1 * 40 + aK] = ph1;
            *(uint4*)&Al[aRow0 * 40 + aK] = pl0;
            *(uint4*)&Al[aRow1 * 40 + aK] = pl1;
            *(uint4*)&Bh[bP * 72 + bN4] = qh;
            *(uint4*)&Bl[bP * 72 + bN4] = ql;
            __syncthreads();
        }
    }

    // epilogue
#pragma unroll
    for (int im = 0; im < 2; im++)
#pragma unroll
        for (int in_ = 0; in_ < 4; in_++) {
            const int row = bm + warpM * 32 + im * 16 + (lane >> 2);
            const int col = bn + warpN * 32 + in_ * 8 + 2 * (lane & 3);
            float2 bb = *(const float2*)(bias + col);
            float v0 = acc[im][in_][0] + bb.x;
            float v1 = acc[im][in_][1] + bb.y;
            float v2 = acc[im][in_][2] + bb.x;
            float v3 = acc[im][in_][3] + bb.y;
            if (EPI == 1) {
                v0 = fmaxf(v0, 0.f); v1 = fmaxf(v1, 0.f);
                v2 = fmaxf(v2, 0.f); v3 = fmaxf(v3, 0.f);
                __nv_bfloat16 h, l;
                __nv_bfloat162 hv, lv;
                split_bf16(v0, h, l); hv.x = h; lv.x = l;
                split_bf16(v1, h, l); hv.y = h; lv.y = l;
                *(__nv_bfloat162*)(Ch + (size_t)row * Nd + col) = hv;
                *(__nv_bfloat162*)(Cl + (size_t)row * Nd + col) = lv;
                split_bf16(v2, h, l); hv.x = h; lv.x = l;
                split_bf16(v3, h, l); hv.y = h; lv.y = l;
                *(__nv_bfloat162*)(Ch + (size_t)(row + 8) * Nd + col) = hv;
                *(__nv_bfloat162*)(Cl + (size_t)(row + 8) * Nd + col) = lv;
            } else {
                float2 o0; o0.x = v0; o0.y = v1;
                float2 o1; o1.x = v2; o1.y = v3;
                *(float2*)(C + (size_t)row * Nd + col)       = o0;
                *(float2*)(C + (size_t)(row + 8) * Nd + col) = o1;
            }
        }
}

// ---------------- attention with smem window ----------------
// Ring graph: nodes [g*32, g*32+32) reference k/v rows (g*32+1 .. g*32+63) mod N.
// Writes bf16 hi/lo directly (consumed only by the Wo GEMM).
__global__ __launch_bounds__(512)
void attn_kernel(const float* __restrict__ q, const float* __restrict__ k,
                 const float* __restrict__ v, const void* __restrict__ ei,
                 const float* __restrict__ edge_attr,
                 const float* __restrict__ We, const float* __restrict__ be,
                 __nv_bfloat16* __restrict__ aoh, __nv_bfloat16* __restrict__ aol)
{
    __shared__ __align__(16) float kS[63 * 68];      // stride 68: float4-aligned rows, banks 4r+d
    __shared__ __align__(16) float vS[63 * 64];
    __shared__ __align__(16) float qS[32 * 64];
    __shared__ __align__(16) float WeS[64];
    __shared__ __align__(16) int   rS[16][32];
    __shared__ __align__(16) float pS[16][32];

    const int g    = blockIdx.x;
    const int h    = blockIdx.y;
    const int base = g * 32;
    const int tid  = threadIdx.x;
    const int lane = tid & 31;
    const int wid  = tid >> 5;    // 0..15

    // stage window
    for (int idx = tid; idx < 63 * 16; idx += 512) {
        const int w = idx >> 4, c = idx & 15;
        int row = base + 1 + w; if (row >= NN) row -= NN;
        float4 kf = *(const float4*)(k + (size_t)row * HID + h * DD + c * 4);
        float4 vf = *(const float4*)(v + (size_t)row * HID + h * DD + c * 4);
        *(float4*)&kS[w * 68 + c * 4] = kf;
        *(float4*)&vS[w * 64 + c * 4] = vf;
    }
    for (int idx = tid; idx < 32 * 16; idx += 512) {
        const int n = idx >> 4, c = idx & 15;
        *(float4*)&qS[n * 64 + c * 4] =
            *(const float4*)(q + (size_t)(base + n) * HID + h * DD + c * 4);
    }
    if (tid < 64) WeS[tid] = We[tid];
    __syncthreads();

    // edge_index dtype probe (int64 vs int32)
    const int probe = ((const int*)ei)[2 * EE - 1];
    const bool is64 = (probe == 0);
    const float beh = be[h];

#pragma unroll
    for (int s = 0; s < 2; s++) {
        const int nloc = wid * 2 + s;
        const int n    = base + nloc;
        const int e    = n * DEG + lane;

        int dst;
        if (is64) dst = (int)((const long long*)ei)[EE + e];
        else      dst = ((const int*)ei)[EE + e];
        int r = dst - base - 1; if (r < 0) r += NN;   // in [0,62]

        // edge bias
        float eb = beh;
        const float* ea = edge_attr + (size_t)e * 16;
        float4 e0 = *(const float4*)(ea);
        float4 e1 = *(const float4*)(ea + 4);
        float4 e2 = *(const float4*)(ea + 8);
        float4 e3 = *(const float4*)(ea + 12);
        eb = fmaf(e0.x, WeS[ 0 * NH + h], eb); eb = fmaf(e0.y, WeS[ 1 * NH + h], eb);
        eb = fmaf(e0.z, WeS[ 2 * NH + h], eb); eb = fmaf(e0.w, WeS[ 3 * NH + h], eb);
        eb = fmaf(e1.x, WeS[ 4 * NH + h], eb); eb = fmaf(e1.y, WeS[ 5 * NH + h], eb);
        eb = fmaf(e1.z, WeS[ 6 * NH + h], eb); eb = fmaf(e1.w, WeS[ 7 * NH + h], eb);
        eb = fmaf(e2.x, WeS[ 8 * NH + h], eb); eb = fmaf(e2.y, WeS[ 9 * NH + h], eb);
        eb = fmaf(e2.z, WeS[10 * NH + h], eb); eb = fmaf(e2.w, WeS[11 * NH + h], eb);
        eb = fmaf(e3.x, WeS[12 * NH + h], eb); eb = fmaf(e3.y, WeS[13 * NH + h], eb);
        eb = fmaf(e3.z, WeS[14 * NH + h], eb); eb = fmaf(e3.w, WeS[15 * NH + h], eb);

        // q . k with float4 smem loads (k rows conflict-free; q broadcast)
        const float4* kr4 = (const float4*)(kS + r * 68);
        const float4* qr4 = (const float4*)(qS + nloc * 64);
        float d0 = 0.f, d1 = 0.f, d2 = 0.f, d3 = 0.f;
#pragma unroll
        for (int d = 0; d < 16; d++) {
            float4 kf = kr4[d];
            float4 qf = qr4[d];
            d0 = fmaf(qf.x, kf.x, d0);
            d1 = fmaf(qf.y, kf.y, d1);
            d2 = fmaf(qf.z, kf.z, d2);
            d3 = fmaf(qf.w, kf.w, d3);
        }
        float logit = ((d0 + d1) + (d2 + d3)) * 0.125f + eb;

        // warp softmax
        float m = logit;
#pragma unroll
        for (int o = 16; o; o >>= 1) m = fmaxf(m, __shfl_xor_sync(0xffffffffu, m, o));
        float p = __expf(logit - m);
        float ssum = p;
#pragma unroll
        for (int o = 16; o; o >>= 1) ssum += __shfl_xor_sync(0xffffffffu, ssum, o);
        const float prob = p / ssum;

        rS[wid][lane] = r;
        pS[wid][lane] = prob;
        __syncwarp();

        float accx = 0.f, accy = 0.f;
#pragma unroll 8
        for (int j = 0; j < DEG; j++) {
            const int   rj = rS[wid][j];
            const float pj = pS[wid][j];
            float2 vf = *(float2*)&vS[rj * 64 + lane * 2];
            accx = fmaf(pj, vf.x, accx);
            accy = fmaf(pj, vf.y, accy);
        }

        __nv_bfloat16 hx, lx, hy, ly;
        split_bf16(accx, hx, lx);
        split_bf16(accy, hy, ly);
        __nv_bfloat162 hv; hv.x = hx; hv.y = hy;
        __nv_bfloat162 lv; lv.x = lx; lv.y = ly;
        *(__nv_bfloat162*)(aoh + (size_t)n * HID + h * DD + lane * 2) = hv;
        *(__nv_bfloat162*)(aol + (size_t)n * HID + h * DD + lane * 2) = lv;
        __syncwarp();
    }
}

// ---------------- residual + LayerNorm (optionally emits bf16 hi/lo) ------
template <bool SPLIT>
__global__ __launch_bounds__(256)
void ln_kernel(const float* __restrict__ x, const float* __restrict__ res,
               const float* __restrict__ g, const float* __restrict__ b,
               float* __restrict__ out,
               __nv_bfloat16* __restrict__ oh, __nv_bfloat16* __restrict__ ol)
{
    const int row = blockIdx.x;
    const int t   = threadIdx.x;
    const size_t idx = (size_t)row * HID + t;

    const float val = x[idx] + res[idx];

    __shared__ __align__(16) float red[16];
    float s  = val;
    float q2 = val * val;
#pragma unroll
    for (int o = 16; o; o >>= 1) {
        s  += __shfl_xor_sync(0xffffffffu, s,  o);
        q2 += __shfl_xor_sync(0xffffffffu, q2, o);
    }
    const int w = t >> 5, l = t & 31;
    if (l == 0) { red[w] = s; red[8 + w] = q2; }
    __syncthreads();

    float ts = 0.f, tq = 0.f;
#pragma unroll
    for (int i = 0; i < 8; i++) { ts += red[i]; tq += red[8 + i]; }

    const float mean = ts * (1.f / HID);
    const float var  = tq * (1.f / HID) - mean * mean;
    const float r    = rsqrtf(var + 1e-5f);

    const float o = (val - mean) * r * g[t] + b[t];
    out[idx] = o;
    if (SPLIT) {
        __nv_bfloat16 h, lo;
        split_bf16(o, h, lo);
        oh[idx] = h;
        ol[idx] = lo;
    }
}

// ---------------- launch ----------------
extern "C" void kernel_launch(void* const* d_in, const int* in_sizes, int n_in,
                              void* d_out, int out_size)
{
    const float* x   = (const float*)d_in[0];
    const void*  ei  = d_in[1];
    const float* ea  = (const float*)d_in[2];
    const float* Wq  = (const float*)d_in[3];
    const float* bq  = (const float*)d_in[4];
    const float* Wk  = (const float*)d_in[5];
    const float* bk  = (const float*)d_in[6];
    const float* Wv  = (const float*)d_in[7];
    const float* bv  = (const float*)d_in[8];
    const float* Wo  = (const float*)d_in[9];
    const float* bo  = (const float*)d_in[10];
    const float* We  = (const float*)d_in[11];
    const float* be  = (const float*)d_in[12];
    const float* g1  = (const float*)d_in[13];
    const float* b1  = (const float*)d_in[14];
    const float* g2  = (const float*)d_in[15];
    const float* b2  = (const float*)d_in[16];
    const float* Wf1 = (const float*)d_in[17];
    const float* bf1 = (const float*)d_in[18];
    const float* Wf2 = (const float*)d_in[19];
    const float* bf2 = (const float*)d_in[20];
    float* out = (float*)d_out;

    __nv_bfloat16 *xh, *xl, *aoh, *aol, *x1h, *x1l, *h1h, *h1l;
    float *q, *k, *v, *ot, *x1, *f2;
    uint32_t *wqh, *wql, *wkh, *wkl, *wvh, *wvl, *woh, *wol, *wf1h, *wf1l, *wf2h, *wf2l;
    cudaGetSymbolAddress((void**)&xh,  g_xh);  cudaGetSymbolAddress((void**)&xl,  g_xl);
    cudaGetSymbolAddress((void**)&q,   g_q);   cudaGetSymbolAddress((void**)&k,   g_k);
    cudaGetSymbolAddress((void**)&v,   g_v);
    cudaGetSymbolAddress((void**)&aoh, g_aoh); cudaGetSymbolAddress((void**)&aol, g_aol);
    cudaGetSymbolAddress((void**)&ot,  g_ot);
    cudaGetSymbolAddress((void**)&x1,  g_x1);
    cudaGetSymbolAddress((void**)&x1h, g_x1h); cudaGetSymbolAddress((void**)&x1l, g_x1l);
    cudaGetSymbolAddress((void**)&h1h, g_h1h); cudaGetSymbolAddress((void**)&h1l, g_h1l);
    cudaGetSymbolAddress((void**)&f2,  g_f2);
    cudaGetSymbolAddress((void**)&wqh, g_wqh); cudaGetSymbolAddress((void**)&wql, g_wql);
    cudaGetSymbolAddress((void**)&wkh, g_wkh); cudaGetSymbolAddress((void**)&wkl, g_wkl);
    cudaGetSymbolAddress((void**)&wvh, g_wvh); cudaGetSymbolAddress((void**)&wvl, g_wvl);
    cudaGetSymbolAddress((void**)&woh, g_woh); cudaGetSymbolAddress((void**)&wol, g_wol);
    cudaGetSymbolAddress((void**)&wf1h, g_wf1h); cudaGetSymbolAddress((void**)&wf1l, g_wf1l);
    cudaGetSymbolAddress((void**)&wf2h, g_wf2h); cudaGetSymbolAddress((void**)&wf2l, g_wf2l);

    const dim3 gQKV(HID / 64, NN / 128);          // (4, 32)
    const dim3 gF1 (HID4 / 64, NN / 128);         // (16, 32)
    const dim3 gF2 (HID / 64, NN / 128);          // (4, 32)

    pack_w_kernel<<<dim3(96, 1, 6), 256>>>(Wq, Wk, Wv, Wo, Wf1, Wf2);
    split_x_kernel<<<(NN * HID / 4 + 255) / 256, 256>>>(x, xh, xl, NN * HID / 4);

    gemm_pk<0><<<gQKV, 256>>>(xh, xl, wqh, wql, bq, q, nullptr, nullptr, NN, HID, HID);
    gemm_pk<0><<<gQKV, 256>>>(xh, xl, wkh, wkl, bk, k, nullptr, nullptr, NN, HID, HID);
    gemm_pk<0><<<gQKV, 256>>>(xh, xl, wvh, wvl, bv, v, nullptr, nullptr, NN, HID, HID);

    attn_kernel<<<dim3(NN / 32, NH), 512>>>(q, k, v, ei, ea, We, be, aoh, aol);

    gemm_pk<0><<<gQKV, 256>>>(aoh, aol, woh, wol, bo, ot, nullptr, nullptr, NN, HID, HID);

    ln_kernel<true><<<NN, HID>>>(x, ot, g1, b1, x1, x1h, x1l);

    gemm_pk<1><<<gF1, 256>>>(x1h, x1l, wf1h, wf1l, bf1, nullptr, h1h, h1l, NN, HID, HID4);
    gemm_pk<0><<<gF2, 256>>>(h1h, h1l, wf2h, wf2l, bf2, f2, nullptr, nullptr, NN, HID4, HID);

    ln_kernel<false><<<NN, HID>>>(x1, f2, g2, b2, out, nullptr, nullptr);
}

// round 17
// speedup vs baseline: 2.2829x; 1.0543x over previous
#include <cuda_runtime.h>
#include <cuda_bf16.h>
#include <math.h>
#include <stdint.h>

// ---------------- problem constants ----------------
#define NN   4096
#define HID  256
#define NH   4
#define DD   64
#define DEG  32
#define EE   (NN * DEG)
#define HID4 (4 * HID)

// ---------------- scratch (device globals; no allocation) ----------------
__device__ __nv_bfloat16 g_xh [NN * HID],  g_xl [NN * HID];
__device__ float         g_q  [NN * HID];
__device__ float         g_k  [NN * HID];
__device__ float         g_v  [NN * HID];
__device__ __nv_bfloat16 g_aoh[NN * HID],  g_aol[NN * HID];
__device__ float         g_ot [NN * HID];
__device__ float         g_x1 [NN * HID];
__device__ __nv_bfloat16 g_x1h[NN * HID],  g_x1l[NN * HID];
__device__ __nv_bfloat16 g_h1h[NN * HID4], g_h1l[NN * HID4];
__device__ float         g_f2 [NN * HID];
// packed weights: uint32 word = (bf16 @ k even, bf16 @ k odd), layout [K/2][N]
__device__ uint32_t g_wqh [HID/2  * HID],  g_wql [HID/2  * HID];
__device__ uint32_t g_wkh [HID/2  * HID],  g_wkl [HID/2  * HID];
__device__ uint32_t g_wvh [HID/2  * HID],  g_wvl [HID/2  * HID];
__device__ uint32_t g_woh [HID/2  * HID],  g_wol [HID/2  * HID];
__device__ uint32_t g_wf1h[HID/2  * HID4], g_wf1l[HID/2  * HID4];
__device__ uint32_t g_wf2h[HID4/2 * HID],  g_wf2l[HID4/2 * HID];

// smem layout constants (2-stage double buffer)
#define A_STG (128 * 40)          // bf16 elems per stage
#define B_STG (16 * 72)           // uint32 words per stage
#define SMEM_BYTES (2*A_STG*2*2 + 2*B_STG*4*2)   // Ah+Al, Bh+Bl = 59392

// ---------------- helpers ----------------
__device__ __forceinline__ uint32_t pk(__nv_bfloat16 a, __nv_bfloat16 b) {
    uint16_t ua = *(uint16_t*)&a, ub = *(uint16_t*)&b;
    return (uint32_t)ua | ((uint32_t)ub << 16);
}
__device__ __forceinline__ void split_bf16(float x, __nv_bfloat16& h, __nv_bfloat16& l) {
    h = __float2bfloat16(x);
    l = __float2bfloat16(x - __bfloat162float(h));
}

#define MMA_BF16(d, a0, a1, a2, a3, b0, b1)                                   \
    asm volatile(                                                             \
        "mma.sync.aligned.m16n8k16.row.col.f32.bf16.bf16.f32 "                \
        "{%0,%1,%2,%3},{%4,%5,%6,%7},{%8,%9},{%0,%1,%2,%3};"                  \
        : "+f"(d[0]), "+f"(d[1]), "+f"(d[2]), "+f"(d[3])                      \
        : "r"(a0), "r"(a1), "r"(a2), "r"(a3), "r"(b0), "r"(b1))

// ---------------- weight packing (once per launch; cheap) ----------------
__global__ void pack_w_kernel(const float* __restrict__ Wq, const float* __restrict__ Wk,
                              const float* __restrict__ Wv, const float* __restrict__ Wo,
                              const float* __restrict__ Wf1, const float* __restrict__ Wf2)
{
    const int z = blockIdx.z;
    const float* W; uint32_t* oh; uint32_t* ol; int K, N;
    switch (z) {
        case 0:  W = Wq;  oh = g_wqh;  ol = g_wql;  K = HID;  N = HID;  break;
        case 1:  W = Wk;  oh = g_wkh;  ol = g_wkl;  K = HID;  N = HID;  break;
        case 2:  W = Wv;  oh = g_wvh;  ol = g_wvl;  K = HID;  N = HID;  break;
        case 3:  W = Wo;  oh = g_woh;  ol = g_wol;  K = HID;  N = HID;  break;
        case 4:  W = Wf1; oh = g_wf1h; ol = g_wf1l; K = HID;  N = HID4; break;
        default: W = Wf2; oh = g_wf2h; ol = g_wf2l; K = HID4; N = HID;  break;
    }
    const int total = (K / 2) * N;
    for (int i = blockIdx.x * blockDim.x + threadIdx.x; i < total;
         i += gridDim.x * blockDim.x) {
        const int p = i / N, n = i - p * N;
        const float a = W[(size_t)(2 * p) * N + n];
        const float b = W[(size_t)(2 * p + 1) * N + n];
        __nv_bfloat16 ah, al, bh, bl;
        split_bf16(a, ah, al);
        split_bf16(b, bh, bl);
        oh[i] = pk(ah, bh);
        ol[i] = pk(al, bl);
    }
}

// ---------------- elementwise fp32 -> bf16 hi/lo split ----------------
__global__ void split_x_kernel(const float* __restrict__ in,
                               __nv_bfloat16* __restrict__ oh,
                               __nv_bfloat16* __restrict__ ol, int n4)
{
    const int i = blockIdx.x * blockDim.x + threadIdx.x;
    if (i >= n4) return;
    float4 v = ((const float4*)in)[i];
    __nv_bfloat16 h0,h1,h2,h3,l0,l1,l2,l3;
    split_bf16(v.x, h0, l0); split_bf16(v.y, h1, l1);
    split_bf16(v.z, h2, l2); split_bf16(v.w, h3, l3);
    uint2 uh; uh.x = pk(h0, h1); uh.y = pk(h2, h3);
    uint2 ul; ul.x = pk(l0, l1); ul.y = pk(l2, l3);
    ((uint2*)oh)[i] = uh;
    ((uint2*)ol)[i] = ul;
}

// ---------------- double-buffered bf16-split GEMM body ----------------
// C(tile bm,bn) = A[M,K] @ B[K,Nd] + bias. 2-stage smem pipeline, one sync/tile.
template <int EPI>
__device__ __forceinline__ void gemm_body(
    const __nv_bfloat16* __restrict__ Agh, const __nv_bfloat16* __restrict__ Agl,
    const uint32_t* __restrict__ Bgh, const uint32_t* __restrict__ Bgl,
    const float* __restrict__ bias,
    float* __restrict__ C, __nv_bfloat16* __restrict__ Ch, __nv_bfloat16* __restrict__ Cl,
    int K, int Nd, int bm, int bn, char* smemRaw)
{
    __nv_bfloat16* Ah = (__nv_bfloat16*)smemRaw;                 // [2][A_STG]
    __nv_bfloat16* Al = Ah + 2 * A_STG;
    uint32_t*      Bh = (uint32_t*)(Al + 2 * A_STG);             // [2][B_STG]
    uint32_t*      Bl = Bh + 2 * B_STG;

    const int tid   = threadIdx.x;
    const int lane  = tid & 31;
    const int wid   = tid >> 5;
    const int warpM = wid >> 1;
    const int warpN = wid & 1;

    const int aRow0 = tid >> 2;
    const int aRow1 = (tid + 256) >> 2;
    const int aK    = (tid & 3) * 8;
    const int bP    = tid >> 4;
    const int bN4   = (tid & 15) * 4;

    float acc[2][4][4];
#pragma unroll
    for (int i = 0; i < 2; i++)
#pragma unroll
        for (int j = 0; j < 4; j++)
#pragma unroll
            for (int r = 0; r < 4; r++) acc[i][j][r] = 0.f;

    const int T = K >> 5;
    uint4 ph0, ph1, pl0, pl1, qh, ql;

    // stage tile 0 into buffer 0
    ph0 = *(const uint4*)(Agh + (size_t)(bm + aRow0) * K + aK);
    ph1 = *(const uint4*)(Agh + (size_t)(bm + aRow1) * K + aK);
    pl0 = *(const uint4*)(Agl + (size_t)(bm + aRow0) * K + aK);
    pl1 = *(const uint4*)(Agl + (size_t)(bm + aRow1) * K + aK);
    qh  = *(const uint4*)(Bgh + (size_t)bP * Nd + bn + bN4);
    ql  = *(const uint4*)(Bgl + (size_t)bP * Nd + bn + bN4);
    *(uint4*)&Ah[aRow0 * 40 + aK] = ph0;
    *(uint4*)&Ah[aRow1 * 40 + aK] = ph1;
    *(uint4*)&Al[aRow0 * 40 + aK] = pl0;
    *(uint4*)&Al[aRow1 * 40 + aK] = pl1;
    *(uint4*)&Bh[bP * 72 + bN4] = qh;
    *(uint4*)&Bl[bP * 72 + bN4] = ql;
    __syncthreads();

    for (int t = 0; t < T; t++) {
        const int cur = t & 1;
        const int nxt = cur ^ 1;
        const bool more = (t + 1 < T);
        if (more) {
            const int k0 = (t + 1) << 5;
            ph0 = *(const uint4*)(Agh + (size_t)(bm + aRow0) * K + k0 + aK);
            ph1 = *(const uint4*)(Agh + (size_t)(bm + aRow1) * K + k0 + aK);
            pl0 = *(const uint4*)(Agl + (size_t)(bm + aRow0) * K + k0 + aK);
            pl1 = *(const uint4*)(Agl + (size_t)(bm + aRow1) * K + k0 + aK);
            qh  = *(const uint4*)(Bgh + (size_t)((k0 >> 1) + bP) * Nd + bn + bN4);
            ql  = *(const uint4*)(Bgl + (size_t)((k0 >> 1) + bP) * Nd + bn + bN4);
        }

        const __nv_bfloat16* AhC = Ah + cur * A_STG;
        const __nv_bfloat16* AlC = Al + cur * A_STG;
        const uint32_t*      BhC = Bh + cur * B_STG;
        const uint32_t*      BlC = Bl + cur * B_STG;

#pragma unroll
        for (int kc = 0; kc < 2; kc++) {
            const int kb = kc * 16 + 2 * (lane & 3);
            uint32_t ahr[2][4], alr[2][4];
#pragma unroll
            for (int im = 0; im < 2; im++) {
                const int r0 = warpM * 32 + im * 16 + (lane >> 2);
                ahr[im][0] = *(uint32_t*)&AhC[(r0    ) * 40 + kb    ];
                ahr[im][1] = *(uint32_t*)&AhC[(r0 + 8) * 40 + kb    ];
                ahr[im][2] = *(uint32_t*)&AhC[(r0    ) * 40 + kb + 8];
                ahr[im][3] = *(uint32_t*)&AhC[(r0 + 8) * 40 + kb + 8];
                alr[im][0] = *(uint32_t*)&AlC[(r0    ) * 40 + kb    ];
                alr[im][1] = *(uint32_t*)&AlC[(r0 + 8) * 40 + kb    ];
                alr[im][2] = *(uint32_t*)&AlC[(r0    ) * 40 + kb + 8];
                alr[im][3] = *(uint32_t*)&AlC[(r0 + 8) * 40 + kb + 8];
            }
            uint32_t bhr[4][2], blr[4][2];
            const int p0 = kc * 8 + (lane & 3);
#pragma unroll
            for (int in_ = 0; in_ < 4; in_++) {
                const int c = warpN * 32 + in_ * 8 + (lane >> 2);
                bhr[in_][0] = BhC[(p0    ) * 72 + c];
                bhr[in_][1] = BhC[(p0 + 4) * 72 + c];
                blr[in_][0] = BlC[(p0    ) * 72 + c];
                blr[in_][1] = BlC[(p0 + 4) * 72 + c];
            }
#pragma unroll
            for (int im = 0; im < 2; im++)
#pragma unroll
                for (int in_ = 0; in_ < 4; in_++) {
                    MMA_BF16(acc[im][in_], ahr[im][0], ahr[im][1], ahr[im][2], ahr[im][3],
                             bhr[in_][0], bhr[in_][1]);
                    MMA_BF16(acc[im][in_], alr[im][0], alr[im][1], alr[im][2], alr[im][3],
                             bhr[in_][0], bhr[in_][1]);
                    MMA_BF16(acc[im][in_], ahr[im][0], ahr[im][1], ahr[im][2], ahr[im][3],
                             blr[in_][0], blr[in_][1]);
                }
        }

        if (more) {
            *(uint4*)&Ah[nxt * A_STG + aRow0 * 40 + aK] = ph0;
            *(uint4*)&Ah[nxt * A_STG + aRow1 * 40 + aK] = ph1;
            *(uint4*)&Al[nxt * A_STG + aRow0 * 40 + aK] = pl0;
            *(uint4*)&Al[nxt * A_STG + aRow1 * 40 + aK] = pl1;
            *(uint4*)&Bh[nxt * B_STG + bP * 72 + bN4] = qh;
            *(uint4*)&Bl[nxt * B_STG + bP * 72 + bN4] = ql;
        }
        __syncthreads();
    }

    // epilogue
#pragma unroll
    for (int im = 0; im < 2; im++)
#pragma unroll
        for (int in_ = 0; in_ < 4; in_++) {
            const int row = bm + warpM * 32 + im * 16 + (lane >> 2);
            const int col = bn + warpN * 32 + in_ * 8 + 2 * (lane & 3);
            float2 bb = *(const float2*)(bias + col);
            float v0 = acc[im][in_][0] + bb.x;
            float v1 = acc[im][in_][1] + bb.y;
            float v2 = acc[im][in_][2] + bb.x;
            float v3 = acc[im][in_][3] + bb.y;
            if (EPI == 1) {
                v0 = fmaxf(v0, 0.f); v1 = fmaxf(v1, 0.f);
                v2 = fmaxf(v2, 0.f); v3 = fmaxf(v3, 0.f);
                __nv_bfloat16 h, l;
                __nv_bfloat162 hv, lv;
                split_bf16(v0, h, l); hv.x = h; lv.x = l;
                split_bf16(v1, h, l); hv.y = h; lv.y = l;
                *(__nv_bfloat162*)(Ch + (size_t)row * Nd + col) = hv;
                *(__nv_bfloat162*)(Cl + (size_t)row * Nd + col) = lv;
                split_bf16(v2, h, l); hv.x = h; lv.x = l;
                split_bf16(v3, h, l); hv.y = h; lv.y = l;
                *(__nv_bfloat162*)(Ch + (size_t)(row + 8) * Nd + col) = hv;
                *(__nv_bfloat162*)(Cl + (size_t)(row + 8) * Nd + col) = lv;
            } else {
                float2 o0; o0.x = v0; o0.y = v1;
                float2 o1; o1.x = v2; o1.y = v3;
                *(float2*)(C + (size_t)row * Nd + col)       = o0;
                *(float2*)(C + (size_t)(row + 8) * Nd + col) = o1;
            }
        }
}

// generic GEMM kernel
template <int EPI>
__global__ __launch_bounds__(256)
void gemm_pk(const __nv_bfloat16* __restrict__ Agh, const __nv_bfloat16* __restrict__ Agl,
             const uint32_t* __restrict__ Bgh, const uint32_t* __restrict__ Bgl,
             const float* __restrict__ bias,
             float* __restrict__ C,
             __nv_bfloat16* __restrict__ Ch, __nv_bfloat16* __restrict__ Cl,
             int K, int Nd)
{
    extern __shared__ char smemRaw[];
    gemm_body<EPI>(Agh, Agl, Bgh, Bgl, bias, C, Ch, Cl,
                   K, Nd, blockIdx.y * 128, blockIdx.x * 64, smemRaw);
}

// fused QKV: grid.x = 12; blocks 0-3 -> Q, 4-7 -> K, 8-11 -> V
__global__ __launch_bounds__(256)
void gemm_qkv(const __nv_bfloat16* __restrict__ Agh, const __nv_bfloat16* __restrict__ Agl,
              const float* __restrict__ bq, const float* __restrict__ bk,
              const float* __restrict__ bv,
              float* __restrict__ q, float* __restrict__ k, float* __restrict__ v)
{
    extern __shared__ char smemRaw[];
    const int seg = blockIdx.x >> 2;
    const int bn  = (blockIdx.x & 3) * 64;
    const uint32_t* Bgh; const uint32_t* Bgl; const float* bias; float* C;
    if (seg == 0)      { Bgh = g_wqh; Bgl = g_wql; bias = bq; C = q; }
    else if (seg == 1) { Bgh = g_wkh; Bgl = g_wkl; bias = bk; C = k; }
    else               { Bgh = g_wvh; Bgl = g_wvl; bias = bv; C = v; }
    gemm_body<0>(Agh, Agl, Bgh, Bgl, bias, C, nullptr, nullptr,
                 HID, HID, blockIdx.y * 128, bn, smemRaw);
}

// ---------------- attention with smem window ----------------
__global__ __launch_bounds__(512)
void attn_kernel(const float* __restrict__ q, const float* __restrict__ k,
                 const float* __restrict__ v, const void* __restrict__ ei,
                 const float* __restrict__ edge_attr,
                 const float* __restrict__ We, const float* __restrict__ be,
                 __nv_bfloat16* __restrict__ aoh, __nv_bfloat16* __restrict__ aol)
{
    __shared__ __align__(16) float kS[63 * 68];
    __shared__ __align__(16) float vS[63 * 64];
    __shared__ __align__(16) float qS[32 * 64];
    __shared__ __align__(16) float WeS[64];
    __shared__ __align__(16) int   rS[16][32];
    __shared__ __align__(16) float pS[16][32];

    const int g    = blockIdx.x;
    const int h    = blockIdx.y;
    const int base = g * 32;
    const int tid  = threadIdx.x;
    const int lane = tid & 31;
    const int wid  = tid >> 5;

    for (int idx = tid; idx < 63 * 16; idx += 512) {
        const int w = idx >> 4, c = idx & 15;
        int row = base + 1 + w; if (row >= NN) row -= NN;
        float4 kf = *(const float4*)(k + (size_t)row * HID + h * DD + c * 4);
        float4 vf = *(const float4*)(v + (size_t)row * HID + h * DD + c * 4);
        *(float4*)&kS[w * 68 + c * 4] = kf;
        *(float4*)&vS[w * 64 + c * 4] = vf;
    }
    for (int idx = tid; idx < 32 * 16; idx += 512) {
        const int n = idx >> 4, c = idx & 15;
        *(float4*)&qS[n * 64 + c * 4] =
            *(const float4*)(q + (size_t)(base + n) * HID + h * DD + c * 4);
    }
    if (tid < 64) WeS[tid] = We[tid];
    __syncthreads();

    const int probe = ((const int*)ei)[2 * EE - 1];
    const bool is64 = (probe == 0);
    const float beh = be[h];

#pragma unroll
    for (int s = 0; s < 2; s++) {
        const int nloc = wid * 2 + s;
        const int n    = base + nloc;
        const int e    = n * DEG + lane;

        int dst;
        if (is64) dst = (int)((const long long*)ei)[EE + e];
        else      dst = ((const int*)ei)[EE + e];
        int r = dst - base - 1; if (r < 0) r += NN;

        float eb = beh;
        const float* ea = edge_attr + (size_t)e * 16;
        float4 e0 = *(const float4*)(ea);
        float4 e1 = *(const float4*)(ea + 4);
        float4 e2 = *(const float4*)(ea + 8);
        float4 e3 = *(const float4*)(ea + 12);
        eb = fmaf(e0.x, WeS[ 0 * NH + h], eb); eb = fmaf(e0.y, WeS[ 1 * NH + h], eb);
        eb = fmaf(e0.z, WeS[ 2 * NH + h], eb); eb = fmaf(e0.w, WeS[ 3 * NH + h], eb);
        eb = fmaf(e1.x, WeS[ 4 * NH + h], eb); eb = fmaf(e1.y, WeS[ 5 * NH + h], eb);
        eb = fmaf(e1.z, WeS[ 6 * NH + h], eb); eb = fmaf(e1.w, WeS[ 7 * NH + h], eb);
        eb = fmaf(e2.x, WeS[ 8 * NH + h], eb); eb = fmaf(e2.y, WeS[ 9 * NH + h], eb);
        eb = fmaf(e2.z, WeS[10 * NH + h], eb); eb = fmaf(e2.w, WeS[11 * NH + h], eb);
        eb = fmaf(e3.x, WeS[12 * NH + h], eb); eb = fmaf(e3.y, WeS[13 * NH + h], eb);
        eb = fmaf(e3.z, WeS[14 * NH + h], eb); eb = fmaf(e3.w, WeS[15 * NH + h], eb);

        const float4* kr4 = (const float4*)(kS + r * 68);
        const float4* qr4 = (const float4*)(qS + nloc * 64);
        float d0 = 0.f, d1 = 0.f, d2 = 0.f, d3 = 0.f;
#pragma unroll
        for (int d = 0; d < 16; d++) {
            float4 kf = kr4[d];
            float4 qf = qr4[d];
            d0 = fmaf(qf.x, kf.x, d0);
            d1 = fmaf(qf.y, kf.y, d1);
            d2 = fmaf(qf.z, kf.z, d2);
            d3 = fmaf(qf.w, kf.w, d3);
        }
        float logit = ((d0 + d1) + (d2 + d3)) * 0.125f + eb;

        float m = logit;
#pragma unroll
        for (int o = 16; o; o >>= 1) m = fmaxf(m, __shfl_xor_sync(0xffffffffu, m, o));
        float p = __expf(logit - m);
        float ssum = p;
#pragma unroll
        for (int o = 16; o; o >>= 1) ssum += __shfl_xor_sync(0xffffffffu, ssum, o);
        const float prob = p / ssum;

        rS[wid][lane] = r;
        pS[wid][lane] = prob;
        __syncwarp();

        float accx = 0.f, accy = 0.f;
#pragma unroll 8
        for (int j = 0; j < DEG; j++) {
            const int   rj = rS[wid][j];
            const float pj = pS[wid][j];
            float2 vf = *(float2*)&vS[rj * 64 + lane * 2];
            accx = fmaf(pj, vf.x, accx);
            accy = fmaf(pj, vf.y, accy);
        }

        __nv_bfloat16 hx, lx, hy, ly;
        split_bf16(accx, hx, lx);
        split_bf16(accy, hy, ly);
        __nv_bfloat162 hv; hv.x = hx; hv.y = hy;
        __nv_bfloat162 lv; lv.x = lx; lv.y = ly;
        *(__nv_bfloat162*)(aoh + (size_t)n * HID + h * DD + lane * 2) = hv;
        *(__nv_bfloat162*)(aol + (size_t)n * HID + h * DD + lane * 2) = lv;
        __syncwarp();
    }
}

// ---------------- residual + LayerNorm (optionally emits bf16 hi/lo) ------
template <bool SPLIT>
__global__ __launch_bounds__(256)
void ln_kernel(const float* __restrict__ x, const float* __restrict__ res,
               const float* __restrict__ g, const float* __restrict__ b,
               float* __restrict__ out,
               __nv_bfloat16* __restrict__ oh, __nv_bfloat16* __restrict__ ol)
{
    const int row = blockIdx.x;
    const int t   = threadIdx.x;
    const size_t idx = (size_t)row * HID + t;

    const float val = x[idx] + res[idx];

    __shared__ __align__(16) float red[16];
    float s  = val;
    float q2 = val * val;
#pragma unroll
    for (int o = 16; o; o >>= 1) {
        s  += __shfl_xor_sync(0xffffffffu, s,  o);
        q2 += __shfl_xor_sync(0xffffffffu, q2, o);
    }
    const int w = t >> 5, l = t & 31;
    if (l == 0) { red[w] = s; red[8 + w] = q2; }
    __syncthreads();

    float ts = 0.f, tq = 0.f;
#pragma unroll
    for (int i = 0; i < 8; i++) { ts += red[i]; tq += red[8 + i]; }

    const float mean = ts * (1.f / HID);
    const float var  = tq * (1.f / HID) - mean * mean;
    const float r    = rsqrtf(var + 1e-5f);

    const float o = (val - mean) * r * g[t] + b[t];
    out[idx] = o;
    if (SPLIT) {
        __nv_bfloat16 h, lo;
        split_bf16(o, h, lo);
        oh[idx] = h;
        ol[idx] = lo;
    }
}

// ---------------- launch ----------------
extern "C" void kernel_launch(void* const* d_in, const int* in_sizes, int n_in,
                              void* d_out, int out_size)
{
    const float* x   = (const float*)d_in[0];
    const void*  ei  = d_in[1];
    const float* ea  = (const float*)d_in[2];
    const float* Wq  = (const float*)d_in[3];
    const float* bq  = (const float*)d_in[4];
    const float* Wk  = (const float*)d_in[5];
    const float* bk  = (const float*)d_in[6];
    const float* Wv  = (const float*)d_in[7];
    const float* bv  = (const float*)d_in[8];
    const float* Wo  = (const float*)d_in[9];
    const float* bo  = (const float*)d_in[10];
    const float* We  = (const float*)d_in[11];
    const float* be  = (const float*)d_in[12];
    const float* g1  = (const float*)d_in[13];
    const float* b1  = (const float*)d_in[14];
    const float* g2  = (const float*)d_in[15];
    const float* b2  = (const float*)d_in[16];
    const float* Wf1 = (const float*)d_in[17];
    const float* bf1 = (const float*)d_in[18];
    const float* Wf2 = (const float*)d_in[19];
    const float* bf2 = (const float*)d_in[20];
    float* out = (float*)d_out;

    __nv_bfloat16 *xh, *xl, *aoh, *aol, *x1h, *x1l, *h1h, *h1l;
    float *q, *k, *v, *ot, *x1, *f2;
    uint32_t *woh, *wol, *wf1h, *wf1l, *wf2h, *wf2l;
    cudaGetSymbolAddress((void**)&xh,  g_xh);  cudaGetSymbolAddress((void**)&xl,  g_xl);
    cudaGetSymbolAddress((void**)&q,   g_q);   cudaGetSymbolAddress((void**)&k,   g_k);
    cudaGetSymbolAddress((void**)&v,   g_v);
    cudaGetSymbolAddress((void**)&aoh, g_aoh); cudaGetSymbolAddress((void**)&aol, g_aol);
    cudaGetSymbolAddress((void**)&ot,  g_ot);
    cudaGetSymbolAddress((void**)&x1,  g_x1);
    cudaGetSymbolAddress((void**)&x1h, g_x1h); cudaGetSymbolAddress((void**)&x1l, g_x1l);
    cudaGetSymbolAddress((void**)&h1h, g_h1h); cudaGetSymbolAddress((void**)&h1l, g_h1l);
    cudaGetSymbolAddress((void**)&f2,  g_f2);
    cudaGetSymbolAddress((void**)&woh, g_woh); cudaGetSymbolAddress((void**)&wol, g_wol);
    cudaGetSymbolAddress((void**)&wf1h, g_wf1h); cudaGetSymbolAddress((void**)&wf1l, g_wf1l);
    cudaGetSymbolAddress((void**)&wf2h, g_wf2h); cudaGetSymbolAddress((void**)&wf2l, g_wf2l);

    // idempotent; called every invocation (no static guards allowed)
    cudaFuncSetAttribute(gemm_qkv,    cudaFuncAttributeMaxDynamicSharedMemorySize, SMEM_BYTES);
    cudaFuncSetAttribute(gemm_pk<0>,  cudaFuncAttributeMaxDynamicSharedMemorySize, SMEM_BYTES);
    cudaFuncSetAttribute(gemm_pk<1>,  cudaFuncAttributeMaxDynamicSharedMemorySize, SMEM_BYTES);

    pack_w_kernel<<<dim3(96, 1, 6), 256>>>(Wq, Wk, Wv, Wo, Wf1, Wf2);
    split_x_kernel<<<(NN * HID / 4 + 255) / 256, 256>>>(x, xh, xl, NN * HID / 4);

    gemm_qkv<<<dim3(12, NN / 128), 256, SMEM_BYTES>>>(xh, xl, bq, bk, bv, q, k, v);

    attn_kernel<<<dim3(NN / 32, NH), 512>>>(q, k, v, ei, ea, We, be, aoh, aol);

    gemm_pk<0><<<dim3(4, NN / 128), 256, SMEM_BYTES>>>(aoh, aol, woh, wol, bo, ot,
                                                       nullptr, nullptr, HID, HID);

    ln_kernel<true><<<NN, HID>>>(x, ot, g1, b1, x1, x1h, x1l);

    gemm_pk<1><<<dim3(16, NN / 128), 256, SMEM_BYTES>>>(x1h, x1l, wf1h, wf1l, bf1,
                                                        nullptr, h1h, h1l, HID, HID4);
    gemm_pk<0><<<dim3(4, NN / 128), 256, SMEM_BYTES>>>(h1h, h1l, wf2h, wf2l, bf2, f2,
                                                       nullptr, nullptr, HID4, HID);

    ln_kernel<false><<<NN, HID>>>(x1, f2, g2, b2, out, nullptr, nullptr);
}